// round 6
// baseline (speedup 1.0000x reference)
#include <cuda_runtime.h>
#include <cstdint>
#include <math.h>

#define B_DIM   8
#define C_DIM   512
#define S_DIM   1024
#define N_HEADS 8
#define DH      64
#define GROUPS  32
#define CPG     16
#define EPS     1e-5f
#define LOG2E   1.4426950408889634f

#define ASTRIDE 36          // gemm smem stage stride (floats) per 32-k row
#define DSTRIDE 133         // gemm smem D-staging stride
#define KSTR    68          // attn smem row stride: 2 chunks of 34 (64 k-values)

// ---------------- device scratch (no allocation allowed) ----------------
__device__ float g_mean[B_DIM * GROUPS];
__device__ float g_rstd[B_DIM * GROUPS];
__device__ float g_xT [(size_t)B_DIM * S_DIM * C_DIM];   // [b,s,c] raw
__device__ float g_xnT[(size_t)B_DIM * S_DIM * C_DIM];   // [b,s,c] group-normed
__device__ float g_Q[(size_t)B_DIM * N_HEADS * S_DIM * DH];   // [b,h,s,d]
__device__ float g_K[(size_t)B_DIM * N_HEADS * S_DIM * DH];   // [b,h,s,d]
__device__ float g_V[(size_t)B_DIM * N_HEADS * DH * S_DIM];   // [b,h,d,s]  (transposed)
__device__ float g_ctx[(size_t)B_DIM * S_DIM * C_DIM];   // [b,s,c]

// ---------------- helpers ----------------
__device__ __forceinline__ uint32_t f2tf32(float f) {
    uint32_t r;
    asm("cvt.rna.tf32.f32 %0, %1;" : "=r"(r) : "f"(f));
    return r;
}

__device__ __forceinline__ void mma_tf32(float c[4], const uint32_t a[4], const uint32_t b[2]) {
    asm volatile(
        "mma.sync.aligned.m16n8k8.row.col.f32.tf32.tf32.f32 "
        "{%0,%1,%2,%3},{%4,%5,%6,%7},{%8,%9},{%0,%1,%2,%3};"
        : "+f"(c[0]), "+f"(c[1]), "+f"(c[2]), "+f"(c[3])
        : "r"(a[0]), "r"(a[1]), "r"(a[2]), "r"(a[3]), "r"(b[0]), "r"(b[1]));
}

// ============================================================================
// 1) GroupNorm statistics
// ============================================================================
__global__ void gn_stats_kernel(const float* __restrict__ x) {
    int bg = blockIdx.x;
    const float4* p = (const float4*)(x + (size_t)bg * CPG * S_DIM);
    const int n4 = CPG * S_DIM / 4;
    float s = 0.f, s2 = 0.f;
    for (int i = threadIdx.x; i < n4; i += 256) {
        float4 v = p[i];
        s  += v.x + v.y + v.z + v.w;
        s2 += v.x * v.x + v.y * v.y + v.z * v.z + v.w * v.w;
    }
    __shared__ float ss[256], sq[256];
    ss[threadIdx.x] = s; sq[threadIdx.x] = s2;
    __syncthreads();
    for (int o = 128; o > 0; o >>= 1) {
        if (threadIdx.x < o) { ss[threadIdx.x] += ss[threadIdx.x + o]; sq[threadIdx.x] += sq[threadIdx.x + o]; }
        __syncthreads();
    }
    if (threadIdx.x == 0) {
        const float invN = 1.f / (CPG * S_DIM);
        float mean = ss[0] * invN;
        float var  = sq[0] * invN - mean * mean;
        g_mean[bg] = mean;
        g_rstd[bg] = rsqrtf(var + EPS);
    }
}

// ============================================================================
// 2) x transpose [b,c,s] -> [b,s,c], raw + GroupNormed (fp32)
// ============================================================================
__global__ void prep_x_kernel(const float* __restrict__ x,
                              const float* __restrict__ gw, const float* __restrict__ gb) {
    __shared__ float t[32][33];
    int b = blockIdx.z, s0 = blockIdx.x * 32, c0 = blockIdx.y * 32;
    const float* xb = x + ((size_t)b * C_DIM + c0) * S_DIM + s0;
    #pragma unroll
    for (int j = 0; j < 4; ++j) {
        int c = threadIdx.y + j * 8;
        t[c][threadIdx.x] = xb[(size_t)c * S_DIM + threadIdx.x];
    }
    __syncthreads();
    int c = c0 + threadIdx.x;
    float w = gw[c], bia = gb[c];
    int gi = b * GROUPS + (c >> 4);
    float mu = g_mean[gi], rs = g_rstd[gi];
    #pragma unroll
    for (int j = 0; j < 4; ++j) {
        int s = s0 + threadIdx.y + j * 8;
        float v = t[threadIdx.x][threadIdx.y + j * 8];
        size_t o = ((size_t)b * S_DIM + s) * C_DIM + c;
        g_xT[o]  = v;
        g_xnT[o] = (v - mu) * rs * w + bia;
    }
}

// ============================================================================
// tf32 mma.sync GEMM core (proven R3): D[128,128] = A[128,512]*B[128,512]^T
// ============================================================================
__device__ __forceinline__ void gemm_mainloop(
    const float* __restrict__ Ag, const float* __restrict__ Bg,
    uint32_t* As, uint32_t* Bs, float acc[4][4][4])
{
    const int tid  = threadIdx.x;
    const int lane = tid & 31;
    const int warp = tid >> 5;
    const int my = warp >> 2, wx = warp & 3;
    const int tg = lane & 3, gp = lane >> 2;
    float4 pa[4], pb[4];

#define LDG_STAGE(k0_) do { \
    _Pragma("unroll") \
    for (int it = 0; it < 4; ++it) { \
        int idx = it * 256 + tid; \
        int row = idx >> 3, cq = idx & 7; \
        pa[it] = *(const float4*)(Ag + (size_t)row * C_DIM + (k0_) + cq * 4); \
        pb[it] = *(const float4*)(Bg + (size_t)row * C_DIM + (k0_) + cq * 4); \
    } \
} while (0)

#define STS_STAGE(buf_) do { \
    uint32_t* Ad = As + (buf_) * (128 * ASTRIDE); \
    uint32_t* Bd = Bs + (buf_) * (128 * ASTRIDE); \
    _Pragma("unroll") \
    for (int it = 0; it < 4; ++it) { \
        int idx = it * 256 + tid; \
        int row = idx >> 3, cq = idx & 7; \
        int base = row * ASTRIDE + (cq >> 1) * 8 + (cq & 1); \
        float av[4] = {pa[it].x, pa[it].y, pa[it].z, pa[it].w}; \
        float bv[4] = {pb[it].x, pb[it].y, pb[it].z, pb[it].w}; \
        _Pragma("unroll") \
        for (int j = 0; j < 4; ++j) { \
            Ad[base + 2 * j] = f2tf32(av[j]); \
            Bd[base + 2 * j] = f2tf32(bv[j]); \
        } \
    } \
} while (0)

    LDG_STAGE(0);
    STS_STAGE(0);
    LDG_STAGE(32);
    __syncthreads();

    const int NSTAGE = C_DIM / 32;
    for (int s = 0; s < NSTAGE; ++s) {
        const uint32_t* Ab = As + (s & 1) * (128 * ASTRIDE);
        const uint32_t* Bb = Bs + (s & 1) * (128 * ASTRIDE);
        #pragma unroll
        for (int k8 = 0; k8 < 4; ++k8) {
            uint32_t af[4][4];
            #pragma unroll
            for (int mi = 0; mi < 4; ++mi) {
                int row = my * 64 + mi * 16 + gp;
                uint2 lo = *(const uint2*)&Ab[row * ASTRIDE + k8 * 8 + tg * 2];
                uint2 hi = *(const uint2*)&Ab[(row + 8) * ASTRIDE + k8 * 8 + tg * 2];
                af[mi][0] = lo.x; af[mi][1] = hi.x; af[mi][2] = lo.y; af[mi][3] = hi.y;
            }
            uint32_t bf[4][2];
            #pragma unroll
            for (int nj = 0; nj < 4; ++nj) {
                int col = wx * 32 + nj * 8 + gp;
                uint2 bb = *(const uint2*)&Bb[col * ASTRIDE + k8 * 8 + tg * 2];
                bf[nj][0] = bb.x; bf[nj][1] = bb.y;
            }
            #pragma unroll
            for (int mi = 0; mi < 4; ++mi)
                #pragma unroll
                for (int nj = 0; nj < 4; ++nj)
                    mma_tf32(acc[mi][nj], af[mi], bf[nj]);
        }
        if (s + 1 < NSTAGE) STS_STAGE((s + 1) & 1);
        if (s + 2 < NSTAGE) LDG_STAGE((s + 2) * 32);
        __syncthreads();
    }
#undef LDG_STAGE
#undef STS_STAGE
}

__device__ __forceinline__ void stage_D(float* Ds, const float acc[4][4][4]) {
    const int lane = threadIdx.x & 31;
    const int warp = threadIdx.x >> 5;
    const int my = warp >> 2, wx = warp & 3;
    const int tg = lane & 3, gp = lane >> 2;
    #pragma unroll
    for (int mi = 0; mi < 4; ++mi) {
        int r = my * 64 + mi * 16 + gp;
        #pragma unroll
        for (int nj = 0; nj < 4; ++nj) {
            int c = wx * 32 + nj * 8 + tg * 2;
            Ds[r * DSTRIDE + c]           = acc[mi][nj][0];
            Ds[r * DSTRIDE + c + 1]       = acc[mi][nj][1];
            Ds[(r + 8) * DSTRIDE + c]     = acc[mi][nj][2];
            Ds[(r + 8) * DSTRIDE + c + 1] = acc[mi][nj][3];
        }
    }
}

// ============================================================================
// 3) QKV projection. Q,K stored [b,h,s,d]; V stored transposed [b,h,d,s].
// ============================================================================
__global__ void __launch_bounds__(256) qkv_mma_kernel(const float* __restrict__ Wq,
                                                      const float* __restrict__ Wk,
                                                      const float* __restrict__ Wv) {
    extern __shared__ uint32_t sm[];
    uint32_t* As = sm;
    uint32_t* Bs = sm + 2 * 128 * ASTRIDE;

    int z = blockIdx.z;
    int mat = z % 3, b = z / 3;
    int co0 = blockIdx.y * 128, s0 = blockIdx.x * 128;

    const float* W  = (mat == 0) ? Wq : (mat == 1) ? Wk : Wv;
    const float* Bt = ((mat == 0) ? g_xnT : g_xT) + (size_t)b * S_DIM * C_DIM;
    const float* Ag = W + (size_t)co0 * C_DIM;
    const float* Bg = Bt + (size_t)s0 * C_DIM;

    float acc[4][4][4] = {};
    gemm_mainloop(Ag, Bg, As, Bs, acc);

    float* Ds = (float*)sm;
    stage_D(Ds, acc);
    __syncthreads();

    int tid = threadIdx.x;
    if (mat == 2) {
        // Vt[b,h,d,s]: rows co_l = (h_l, d), cols = s  (coalesced along s)
        #pragma unroll
        for (int it = 0; it < 16; ++it) {
            int i = it * 256 + tid;
            int s4 = (i & 31) * 4, co_l = i >> 5;
            int h = (co0 >> 6) + (co_l >> 6), d = co_l & 63;
            float4 v = make_float4(Ds[co_l * DSTRIDE + s4],     Ds[co_l * DSTRIDE + s4 + 1],
                                   Ds[co_l * DSTRIDE + s4 + 2], Ds[co_l * DSTRIDE + s4 + 3]);
            *(float4*)&g_V[(((size_t)(b * N_HEADS + h)) * DH + d) * S_DIM + s0 + s4] = v;
        }
    } else {
        float* dst = (mat == 0) ? g_Q : g_K;
        #pragma unroll
        for (int it = 0; it < 16; ++it) {
            int i = it * 256 + tid;
            int d0  = (i & 15) * 4;
            int s_l = (i >> 4) & 127;
            int h_l = i >> 11;
            int row = h_l * 64 + d0;
            float4 v = make_float4(Ds[row * DSTRIDE + s_l],
                                   Ds[(row + 1) * DSTRIDE + s_l],
                                   Ds[(row + 2) * DSTRIDE + s_l],
                                   Ds[(row + 3) * DSTRIDE + s_l]);
            int h = (co0 >> 6) + h_l;
            int s = s0 + s_l;
            *(float4*)&dst[(((size_t)(b * N_HEADS + h)) * S_DIM + s) * DH + d0] = v;
        }
    }
}

// ============================================================================
// 4) Tensor-core flash attention v2.
//    q-tile 128, kv-tile 64, 8 warps; warp tile = 16 q-rows x full kv width.
//    Softmax fully register-resident (row stats via 2x shfl); P written once.
//    Smem 104.4KB -> 2 CTAs/SM.
// ============================================================================
__global__ void __launch_bounds__(256, 2) attn_mma_kernel() {
    extern __shared__ float sm_f[];
    uint32_t* Qs = (uint32_t*)sm_f;          // 128 * KSTR
    uint32_t* Ks = Qs + 128 * KSTR;          // 64 * KSTR
    uint32_t* Vs = Ks + 64 * KSTR;           // 64 * KSTR  ([d][kv])
    uint32_t* Ps = Vs + 64 * KSTR;           // 128 * KSTR (P tf32; also D staging)

    const int tid = threadIdx.x;
    const int lane = tid & 31, warp = tid >> 5;
    const int tg = lane & 3, gp = lane >> 2;
    const int bh = blockIdx.y;
    const int b = bh >> 3, h = bh & 7;
    const int s0 = blockIdx.x * 128;
    const int r0 = warp * 16 + gp, r1 = r0 + 8;     // this thread's two q-rows

    const float* Qg  = g_Q + (size_t)bh * S_DIM * DH;
    const float* Kg  = g_K + (size_t)bh * S_DIM * DH;
    const float* Vtg = g_V + (size_t)bh * DH * S_DIM;   // [d][s]

    // Q tile: tf32, permuted, scaled by 1/8 * log2(e)  (exp2-domain softmax)
    const float qscale = 0.125f * LOG2E;
    #pragma unroll
    for (int it = 0; it < 8; ++it) {
        int idx = it * 256 + tid;
        int row = idx >> 4, f4 = idx & 15;
        float4 v = *(const float4*)(Qg + (size_t)(s0 + row) * DH + f4 * 4);
        int chunk = f4 >> 3, cq = f4 & 7;
        uint32_t* p = Qs + row * KSTR + chunk * 34 + ((cq >> 1) << 3) + (cq & 1);
        p[0] = f2tf32(v.x * qscale); p[2] = f2tf32(v.y * qscale);
        p[4] = f2tf32(v.z * qscale); p[6] = f2tf32(v.w * qscale);
    }

    float m0 = -1e30f, m1 = -1e30f, l0 = 0.f, l1 = 0.f;
    float o_acc[8][4] = {};

    for (int t0 = 0; t0 < S_DIM; t0 += 64) {
        __syncthreads();   // prev PV reads of Ps/Vs done (iter0: Qs visible)
        // K tile [kv=64][d=64]
        #pragma unroll
        for (int it = 0; it < 4; ++it) {
            int idx = it * 256 + tid;
            int row = idx >> 4, f4 = idx & 15;
            float4 v = *(const float4*)(Kg + (size_t)(t0 + row) * DH + f4 * 4);
            int chunk = f4 >> 3, cq = f4 & 7;
            uint32_t* p = Ks + row * KSTR + chunk * 34 + ((cq >> 1) << 3) + (cq & 1);
            p[0] = f2tf32(v.x); p[2] = f2tf32(v.y); p[4] = f2tf32(v.z); p[6] = f2tf32(v.w);
        }
        // V tile [d=64][kv=64]
        #pragma unroll
        for (int it = 0; it < 4; ++it) {
            int idx = it * 256 + tid;
            int d = idx >> 4, f4 = idx & 15;
            float4 v = *(const float4*)(Vtg + (size_t)d * S_DIM + t0 + f4 * 4);
            int chunk = f4 >> 3, cq = f4 & 7;
            uint32_t* p = Vs + d * KSTR + chunk * 34 + ((cq >> 1) << 3) + (cq & 1);
            p[0] = f2tf32(v.x); p[2] = f2tf32(v.y); p[4] = f2tf32(v.z); p[6] = f2tf32(v.w);
        }
        __syncthreads();

        // ---- S = Q K^T : warp covers rows r0/r1, all 64 kv cols ----
        float s_acc[8][4] = {};
        #pragma unroll
        for (int k8 = 0; k8 < 8; ++k8) {
            int koff = (k8 >> 2) * 34 + (k8 & 3) * 8 + tg * 2;
            uint2 lo = *(const uint2*)&Qs[r0 * KSTR + koff];
            uint2 hi = *(const uint2*)&Qs[r1 * KSTR + koff];
            uint32_t af[4] = {lo.x, hi.x, lo.y, hi.y};
            #pragma unroll
            for (int nj = 0; nj < 8; ++nj) {
                int col = nj * 8 + gp;
                uint2 bb = *(const uint2*)&Ks[col * KSTR + koff];
                uint32_t bf[2] = {bb.x, bb.y};
                mma_tf32(s_acc[nj], af, bf);
            }
        }

        // ---- register softmax (log2 domain) ----
        float mx0 = s_acc[0][0], mx1 = s_acc[0][2];
        #pragma unroll
        for (int nj = 0; nj < 8; ++nj) {
            mx0 = fmaxf(mx0, fmaxf(s_acc[nj][0], s_acc[nj][1]));
            mx1 = fmaxf(mx1, fmaxf(s_acc[nj][2], s_acc[nj][3]));
        }
        mx0 = fmaxf(mx0, __shfl_xor_sync(0xffffffffu, mx0, 1));
        mx0 = fmaxf(mx0, __shfl_xor_sync(0xffffffffu, mx0, 2));
        mx1 = fmaxf(mx1, __shfl_xor_sync(0xffffffffu, mx1, 1));
        mx1 = fmaxf(mx1, __shfl_xor_sync(0xffffffffu, mx1, 2));
        float m0n = fmaxf(m0, mx0), m1n = fmaxf(m1, mx1);
        float c0 = exp2f(m0 - m0n), c1 = exp2f(m1 - m1n);
        float sum0 = 0.f, sum1 = 0.f;
        #pragma unroll
        for (int nj = 0; nj < 8; ++nj) {
            float p0 = exp2f(s_acc[nj][0] - m0n);
            float p1 = exp2f(s_acc[nj][1] - m0n);
            float p2 = exp2f(s_acc[nj][2] - m1n);
            float p3 = exp2f(s_acc[nj][3] - m1n);
            s_acc[nj][0] = p0; s_acc[nj][1] = p1;
            s_acc[nj][2] = p2; s_acc[nj][3] = p3;
            sum0 += p0 + p1; sum1 += p2 + p3;
        }
        sum0 += __shfl_xor_sync(0xffffffffu, sum0, 1);
        sum0 += __shfl_xor_sync(0xffffffffu, sum0, 2);
        sum1 += __shfl_xor_sync(0xffffffffu, sum1, 1);
        sum1 += __shfl_xor_sync(0xffffffffu, sum1, 2);
        l0 = l0 * c0 + sum0; l1 = l1 * c1 + sum1;
        m0 = m0n; m1 = m1n;
        #pragma unroll
        for (int nj = 0; nj < 8; ++nj) {
            o_acc[nj][0] *= c0; o_acc[nj][1] *= c0;
            o_acc[nj][2] *= c1; o_acc[nj][3] *= c1;
        }
        // write P (permuted tf32): c0col = nj*8 + 2*tg -> off = (nj&3)*8 + (tg>>1) + 4*(tg&1)
        #pragma unroll
        for (int nj = 0; nj < 8; ++nj) {
            int base = (nj >> 2) * 34 + (nj & 3) * 8 + (tg >> 1) + 4 * (tg & 1);
            uint32_t* p0 = Ps + r0 * KSTR + base;
            p0[0] = f2tf32(s_acc[nj][0]); p0[2] = f2tf32(s_acc[nj][1]);
            uint32_t* p1 = Ps + r1 * KSTR + base;
            p1[0] = f2tf32(s_acc[nj][2]); p1[2] = f2tf32(s_acc[nj][3]);
        }
        __syncthreads();

        // ---- O += P V ----
        #pragma unroll
        for (int k8 = 0; k8 < 8; ++k8) {
            int koff = (k8 >> 2) * 34 + (k8 & 3) * 8 + tg * 2;
            uint2 lo = *(const uint2*)&Ps[r0 * KSTR + koff];
            uint2 hi = *(const uint2*)&Ps[r1 * KSTR + koff];
            uint32_t af[4] = {lo.x, hi.x, lo.y, hi.y};
            #pragma unroll
            for (int nj = 0; nj < 8; ++nj) {
                int col = nj * 8 + gp;     // d index
                uint2 bb = *(const uint2*)&Vs[col * KSTR + koff];
                uint32_t bf[2] = {bb.x, bb.y};
                mma_tf32(o_acc[nj], af, bf);
            }
        }
    }

    // ---- epilogue: normalize, stage (stride KSTR), coalesced ctx store ----
    __syncthreads();
    float* Ds = (float*)Ps;
    float inv0 = 1.f / l0, inv1 = 1.f / l1;
    #pragma unroll
    for (int nj = 0; nj < 8; ++nj) {
        int c = nj * 8 + tg * 2;
        Ds[r0 * KSTR + c]     = o_acc[nj][0] * inv0;
        Ds[r0 * KSTR + c + 1] = o_acc[nj][1] * inv0;
        Ds[r1 * KSTR + c]     = o_acc[nj][2] * inv1;
        Ds[r1 * KSTR + c + 1] = o_acc[nj][3] * inv1;
    }
    __syncthreads();
    float* cb = g_ctx + ((size_t)b * S_DIM + s0) * C_DIM + h * DH;
    #pragma unroll
    for (int it = 0; it < 8; ++it) {
        int idx = it * 256 + tid;
        int r = idx >> 4, c4 = (idx & 15) * 4;
        float4 v = make_float4(Ds[r * KSTR + c4],     Ds[r * KSTR + c4 + 1],
                               Ds[r * KSTR + c4 + 2], Ds[r * KSTR + c4 + 3]);
        *(float4*)(cb + (size_t)r * C_DIM + c4) = v;
    }
}

// ============================================================================
// 5) Output projection (unchanged)
// ============================================================================
__global__ void __launch_bounds__(256) out_mma_kernel(const float* __restrict__ Wo,
                                                      const float* __restrict__ bo,
                                                      float* __restrict__ out) {
    extern __shared__ uint32_t sm[];
    uint32_t* As = sm;
    uint32_t* Bs = sm + 2 * 128 * ASTRIDE;

    int b = blockIdx.z;
    int co0 = blockIdx.y * 128, s0 = blockIdx.x * 128;

    const float* Ag = Wo + (size_t)co0 * C_DIM;
    const float* Bg = g_ctx + ((size_t)b * S_DIM + s0) * C_DIM;

    float acc[4][4][4] = {};
    gemm_mainloop(Ag, Bg, As, Bs, acc);

    float* Ds = (float*)sm;
    stage_D(Ds, acc);
    __syncthreads();

    int tid = threadIdx.x;
    #pragma unroll
    for (int it = 0; it < 16; ++it) {
        int i = it * 256 + tid;
        int s4   = (i & 31) * 4;
        int co_l = i >> 5;
        float bias = bo[co0 + co_l];
        float4 v = make_float4(Ds[co_l * DSTRIDE + s4]     + bias,
                               Ds[co_l * DSTRIDE + s4 + 1] + bias,
                               Ds[co_l * DSTRIDE + s4 + 2] + bias,
                               Ds[co_l * DSTRIDE + s4 + 3] + bias);
        *(float4*)&out[((size_t)b * C_DIM + co0 + co_l) * S_DIM + s0 + s4] = v;
    }
}

// ============================================================================
extern "C" void kernel_launch(void* const* d_in, const int* in_sizes, int n_in,
                              void* d_out, int out_size) {
    const float* x    = (const float*)d_in[0];
    const float* gn_w = (const float*)d_in[1];
    const float* gn_b = (const float*)d_in[2];
    const float* Wq   = (const float*)d_in[3];
    const float* Wk   = (const float*)d_in[4];
    const float* Wv   = (const float*)d_in[5];
    const float* Wo   = (const float*)d_in[6];
    const float* bo   = (const float*)d_in[7];
    float* out = (float*)d_out;

    const int gemm_smem = 4 * 128 * ASTRIDE * (int)sizeof(float);   // 73728 B
    const int attn_smem = (128 * KSTR + 64 * KSTR + 64 * KSTR + 128 * KSTR)
                          * (int)sizeof(float);                     // 104448 B

    gn_stats_kernel<<<B_DIM * GROUPS, 256>>>(x);
    prep_x_kernel<<<dim3(S_DIM / 32, C_DIM / 32, B_DIM), dim3(32, 8)>>>(x, gn_w, gn_b);

    cudaFuncSetAttribute(qkv_mma_kernel, cudaFuncAttributeMaxDynamicSharedMemorySize, gemm_smem);
    qkv_mma_kernel<<<dim3(S_DIM / 128, C_DIM / 128, B_DIM * 3), 256, gemm_smem>>>(Wq, Wk, Wv);

    cudaFuncSetAttribute(attn_mma_kernel, cudaFuncAttributeMaxDynamicSharedMemorySize, attn_smem);
    attn_mma_kernel<<<dim3(S_DIM / 128, B_DIM * N_HEADS), 256, attn_smem>>>();

    cudaFuncSetAttribute(out_mma_kernel, cudaFuncAttributeMaxDynamicSharedMemorySize, gemm_smem);
    out_mma_kernel<<<dim3(S_DIM / 128, C_DIM / 128, B_DIM), 256, gemm_smem>>>(Wo, bo, out);
}

// round 7
// speedup vs baseline: 1.1310x; 1.1310x over previous
#include <cuda_runtime.h>
#include <cstdint>
#include <math.h>

#define B_DIM   8
#define C_DIM   512
#define S_DIM   1024
#define N_HEADS 8
#define DH      64
#define GROUPS  32
#define CPG     16
#define EPS     1e-5f
#define LOG2E   1.4426950408889634f

#define ASTRIDE 36          // gemm smem stage stride (floats) per 32-k row
#define DSTRIDE 133         // gemm smem D-staging stride
#define KSTR    68          // attn Q/K smem row stride (2 chunks of 34)
#define VSTR    140         // attn V smem row stride (4 chunks of 34 + pad)

// ---------------- device scratch (no allocation allowed) ----------------
__device__ float g_mean[B_DIM * GROUPS];
__device__ float g_rstd[B_DIM * GROUPS];
__device__ float g_xT [(size_t)B_DIM * S_DIM * C_DIM];   // [b,s,c] raw
__device__ float g_xnT[(size_t)B_DIM * S_DIM * C_DIM];   // [b,s,c] group-normed
__device__ float g_Q[(size_t)B_DIM * N_HEADS * S_DIM * DH];   // [b,h,s,d]
__device__ float g_K[(size_t)B_DIM * N_HEADS * S_DIM * DH];   // [b,h,s,d]
__device__ float g_V[(size_t)B_DIM * N_HEADS * DH * S_DIM];   // [b,h,d,s]  (transposed)
__device__ float g_ctx[(size_t)B_DIM * S_DIM * C_DIM];   // [b,s,c]

// ---------------- helpers ----------------
__device__ __forceinline__ uint32_t f2tf32(float f) {
    uint32_t r;
    asm("cvt.rna.tf32.f32 %0, %1;" : "=r"(r) : "f"(f));
    return r;
}

__device__ __forceinline__ void mma_tf32(float c[4], const uint32_t a[4], const uint32_t b[2]) {
    asm volatile(
        "mma.sync.aligned.m16n8k8.row.col.f32.tf32.tf32.f32 "
        "{%0,%1,%2,%3},{%4,%5,%6,%7},{%8,%9},{%0,%1,%2,%3};"
        : "+f"(c[0]), "+f"(c[1]), "+f"(c[2]), "+f"(c[3])
        : "r"(a[0]), "r"(a[1]), "r"(a[2]), "r"(a[3]), "r"(b[0]), "r"(b[1]));
}

// ============================================================================
// 1) GroupNorm statistics
// ============================================================================
__global__ void gn_stats_kernel(const float* __restrict__ x) {
    int bg = blockIdx.x;
    const float4* p = (const float4*)(x + (size_t)bg * CPG * S_DIM);
    const int n4 = CPG * S_DIM / 4;
    float s = 0.f, s2 = 0.f;
    for (int i = threadIdx.x; i < n4; i += 256) {
        float4 v = p[i];
        s  += v.x + v.y + v.z + v.w;
        s2 += v.x * v.x + v.y * v.y + v.z * v.z + v.w * v.w;
    }
    __shared__ float ss[256], sq[256];
    ss[threadIdx.x] = s; sq[threadIdx.x] = s2;
    __syncthreads();
    for (int o = 128; o > 0; o >>= 1) {
        if (threadIdx.x < o) { ss[threadIdx.x] += ss[threadIdx.x + o]; sq[threadIdx.x] += sq[threadIdx.x + o]; }
        __syncthreads();
    }
    if (threadIdx.x == 0) {
        const float invN = 1.f / (CPG * S_DIM);
        float mean = ss[0] * invN;
        float var  = sq[0] * invN - mean * mean;
        g_mean[bg] = mean;
        g_rstd[bg] = rsqrtf(var + EPS);
    }
}

// ============================================================================
// 2) x transpose [b,c,s] -> [b,s,c], raw + GroupNormed (fp32)
// ============================================================================
__global__ void prep_x_kernel(const float* __restrict__ x,
                              const float* __restrict__ gw, const float* __restrict__ gb) {
    __shared__ float t[32][33];
    int b = blockIdx.z, s0 = blockIdx.x * 32, c0 = blockIdx.y * 32;
    const float* xb = x + ((size_t)b * C_DIM + c0) * S_DIM + s0;
    #pragma unroll
    for (int j = 0; j < 4; ++j) {
        int c = threadIdx.y + j * 8;
        t[c][threadIdx.x] = xb[(size_t)c * S_DIM + threadIdx.x];
    }
    __syncthreads();
    int c = c0 + threadIdx.x;
    float w = gw[c], bia = gb[c];
    int gi = b * GROUPS + (c >> 4);
    float mu = g_mean[gi], rs = g_rstd[gi];
    #pragma unroll
    for (int j = 0; j < 4; ++j) {
        int s = s0 + threadIdx.y + j * 8;
        float v = t[threadIdx.x][threadIdx.y + j * 8];
        size_t o = ((size_t)b * S_DIM + s) * C_DIM + c;
        g_xT[o]  = v;
        g_xnT[o] = (v - mu) * rs * w + bia;
    }
}

// ============================================================================
// tf32 mma.sync GEMM core (proven R3): D[128,128] = A[128,512]*B[128,512]^T
// ============================================================================
__device__ __forceinline__ void gemm_mainloop(
    const float* __restrict__ Ag, const float* __restrict__ Bg,
    uint32_t* As, uint32_t* Bs, float acc[4][4][4])
{
    const int tid  = threadIdx.x;
    const int lane = tid & 31;
    const int warp = tid >> 5;
    const int my = warp >> 2, wx = warp & 3;
    const int tg = lane & 3, gp = lane >> 2;
    float4 pa[4], pb[4];

#define LDG_STAGE(k0_) do { \
    _Pragma("unroll") \
    for (int it = 0; it < 4; ++it) { \
        int idx = it * 256 + tid; \
        int row = idx >> 3, cq = idx & 7; \
        pa[it] = *(const float4*)(Ag + (size_t)row * C_DIM + (k0_) + cq * 4); \
        pb[it] = *(const float4*)(Bg + (size_t)row * C_DIM + (k0_) + cq * 4); \
    } \
} while (0)

#define STS_STAGE(buf_) do { \
    uint32_t* Ad = As + (buf_) * (128 * ASTRIDE); \
    uint32_t* Bd = Bs + (buf_) * (128 * ASTRIDE); \
    _Pragma("unroll") \
    for (int it = 0; it < 4; ++it) { \
        int idx = it * 256 + tid; \
        int row = idx >> 3, cq = idx & 7; \
        int base = row * ASTRIDE + (cq >> 1) * 8 + (cq & 1); \
        float av[4] = {pa[it].x, pa[it].y, pa[it].z, pa[it].w}; \
        float bv[4] = {pb[it].x, pb[it].y, pb[it].z, pb[it].w}; \
        _Pragma("unroll") \
        for (int j = 0; j < 4; ++j) { \
            Ad[base + 2 * j] = f2tf32(av[j]); \
            Bd[base + 2 * j] = f2tf32(bv[j]); \
        } \
    } \
} while (0)

    LDG_STAGE(0);
    STS_STAGE(0);
    LDG_STAGE(32);
    __syncthreads();

    const int NSTAGE = C_DIM / 32;
    for (int s = 0; s < NSTAGE; ++s) {
        const uint32_t* Ab = As + (s & 1) * (128 * ASTRIDE);
        const uint32_t* Bb = Bs + (s & 1) * (128 * ASTRIDE);
        #pragma unroll
        for (int k8 = 0; k8 < 4; ++k8) {
            uint32_t af[4][4];
            #pragma unroll
            for (int mi = 0; mi < 4; ++mi) {
                int row = my * 64 + mi * 16 + gp;
                uint2 lo = *(const uint2*)&Ab[row * ASTRIDE + k8 * 8 + tg * 2];
                uint2 hi = *(const uint2*)&Ab[(row + 8) * ASTRIDE + k8 * 8 + tg * 2];
                af[mi][0] = lo.x; af[mi][1] = hi.x; af[mi][2] = lo.y; af[mi][3] = hi.y;
            }
            uint32_t bf[4][2];
            #pragma unroll
            for (int nj = 0; nj < 4; ++nj) {
                int col = wx * 32 + nj * 8 + gp;
                uint2 bb = *(const uint2*)&Bb[col * ASTRIDE + k8 * 8 + tg * 2];
                bf[nj][0] = bb.x; bf[nj][1] = bb.y;
            }
            #pragma unroll
            for (int mi = 0; mi < 4; ++mi)
                #pragma unroll
                for (int nj = 0; nj < 4; ++nj)
                    mma_tf32(acc[mi][nj], af[mi], bf[nj]);
        }
        if (s + 1 < NSTAGE) STS_STAGE((s + 1) & 1);
        if (s + 2 < NSTAGE) LDG_STAGE((s + 2) * 32);
        __syncthreads();
    }
#undef LDG_STAGE
#undef STS_STAGE
}

__device__ __forceinline__ void stage_D(float* Ds, const float acc[4][4][4]) {
    const int lane = threadIdx.x & 31;
    const int warp = threadIdx.x >> 5;
    const int my = warp >> 2, wx = warp & 3;
    const int tg = lane & 3, gp = lane >> 2;
    #pragma unroll
    for (int mi = 0; mi < 4; ++mi) {
        int r = my * 64 + mi * 16 + gp;
        #pragma unroll
        for (int nj = 0; nj < 4; ++nj) {
            int c = wx * 32 + nj * 8 + tg * 2;
            Ds[r * DSTRIDE + c]           = acc[mi][nj][0];
            Ds[r * DSTRIDE + c + 1]       = acc[mi][nj][1];
            Ds[(r + 8) * DSTRIDE + c]     = acc[mi][nj][2];
            Ds[(r + 8) * DSTRIDE + c + 1] = acc[mi][nj][3];
        }
    }
}

// ============================================================================
// 3) QKV projection. Q,K stored [b,h,s,d]; V stored transposed [b,h,d,s].
// ============================================================================
__global__ void __launch_bounds__(256) qkv_mma_kernel(const float* __restrict__ Wq,
                                                      const float* __restrict__ Wk,
                                                      const float* __restrict__ Wv) {
    extern __shared__ uint32_t sm[];
    uint32_t* As = sm;
    uint32_t* Bs = sm + 2 * 128 * ASTRIDE;

    int z = blockIdx.z;
    int mat = z % 3, b = z / 3;
    int co0 = blockIdx.y * 128, s0 = blockIdx.x * 128;

    const float* W  = (mat == 0) ? Wq : (mat == 1) ? Wk : Wv;
    const float* Bt = ((mat == 0) ? g_xnT : g_xT) + (size_t)b * S_DIM * C_DIM;
    const float* Ag = W + (size_t)co0 * C_DIM;
    const float* Bg = Bt + (size_t)s0 * C_DIM;

    float acc[4][4][4] = {};
    gemm_mainloop(Ag, Bg, As, Bs, acc);

    float* Ds = (float*)sm;
    stage_D(Ds, acc);
    __syncthreads();

    int tid = threadIdx.x;
    if (mat == 2) {
        // Vt[b,h,d,s]: rows co_l = (h_l, d), cols = s  (coalesced along s)
        #pragma unroll
        for (int it = 0; it < 16; ++it) {
            int i = it * 256 + tid;
            int s4 = (i & 31) * 4, co_l = i >> 5;
            int h = (co0 >> 6) + (co_l >> 6), d = co_l & 63;
            float4 v = make_float4(Ds[co_l * DSTRIDE + s4],     Ds[co_l * DSTRIDE + s4 + 1],
                                   Ds[co_l * DSTRIDE + s4 + 2], Ds[co_l * DSTRIDE + s4 + 3]);
            *(float4*)&g_V[(((size_t)(b * N_HEADS + h)) * DH + d) * S_DIM + s0 + s4] = v;
        }
    } else {
        float* dst = (mat == 0) ? g_Q : g_K;
        #pragma unroll
        for (int it = 0; it < 16; ++it) {
            int i = it * 256 + tid;
            int d0  = (i & 15) * 4;
            int s_l = (i >> 4) & 127;
            int h_l = i >> 11;
            int row = h_l * 64 + d0;
            float4 v = make_float4(Ds[row * DSTRIDE + s_l],
                                   Ds[(row + 1) * DSTRIDE + s_l],
                                   Ds[(row + 2) * DSTRIDE + s_l],
                                   Ds[(row + 3) * DSTRIDE + s_l]);
            int h = (co0 >> 6) + h_l;
            int s = s0 + s_l;
            *(float4*)&dst[(((size_t)(b * N_HEADS + h)) * S_DIM + s) * DH + d0] = v;
        }
    }
}

// ============================================================================
// 4) Tensor-core flash attention v3 (FA2-style, no P smem round trip).
//    q-tile 128, kv-tile 128, 8 warps; warp tile = 16 q-rows x full kv.
//    Register softmax; S fragments fed directly as PV A-fragments (V stored
//    linearly in-chunk so k-slots agree). Smem 105.5KB -> 2 CTAs/SM.
// ============================================================================
__global__ void __launch_bounds__(256, 2) attn_mma_kernel() {
    extern __shared__ float sm_f[];
    uint32_t* Qs = (uint32_t*)sm_f;          // 128 * KSTR
    uint32_t* Ks = Qs + 128 * KSTR;          // 128 * KSTR
    uint32_t* Vs = Ks + 128 * KSTR;          // 64 * VSTR   ([d][kv], linear chunks)

    const int tid = threadIdx.x;
    const int lane = tid & 31, warp = tid >> 5;
    const int tg = lane & 3, gp = lane >> 2;
    const int bh = blockIdx.y;
    const int b = bh >> 3, h = bh & 7;
    const int s0 = blockIdx.x * 128;
    const int r0 = warp * 16 + gp, r1 = r0 + 8;     // this thread's two q-rows

    const float* Qg  = g_Q + (size_t)bh * S_DIM * DH;
    const float* Kg  = g_K + (size_t)bh * S_DIM * DH;
    const float* Vtg = g_V + (size_t)bh * DH * S_DIM;   // [d][s]

    // Q tile: tf32, permuted, scaled by 1/8 * log2(e)
    const float qscale = 0.125f * LOG2E;
    #pragma unroll
    for (int it = 0; it < 8; ++it) {
        int idx = it * 256 + tid;
        int row = idx >> 4, f4 = idx & 15;
        float4 v = *(const float4*)(Qg + (size_t)(s0 + row) * DH + f4 * 4);
        int chunk = f4 >> 3, cq = f4 & 7;
        uint32_t* p = Qs + row * KSTR + chunk * 34 + ((cq >> 1) << 3) + (cq & 1);
        p[0] = f2tf32(v.x * qscale); p[2] = f2tf32(v.y * qscale);
        p[4] = f2tf32(v.z * qscale); p[6] = f2tf32(v.w * qscale);
    }

    float m0 = -1e30f, m1 = -1e30f, l0 = 0.f, l1 = 0.f;
    float o_acc[8][4] = {};

    for (int t0 = 0; t0 < S_DIM; t0 += 128) {
        __syncthreads();   // prev PV reads of Ks/Vs done (iter0: Qs visible)
        // K tile [kv=128][d=64], permuted (matches Q convention)
        #pragma unroll
        for (int it = 0; it < 8; ++it) {
            int idx = it * 256 + tid;
            int row = idx >> 4, f4 = idx & 15;
            float4 v = *(const float4*)(Kg + (size_t)(t0 + row) * DH + f4 * 4);
            int chunk = f4 >> 3, cq = f4 & 7;
            uint32_t* p = Ks + row * KSTR + chunk * 34 + ((cq >> 1) << 3) + (cq & 1);
            p[0] = f2tf32(v.x); p[2] = f2tf32(v.y); p[4] = f2tf32(v.z); p[6] = f2tf32(v.w);
        }
        // V tile [d=64][kv=128], LINEAR within chunks (identity k-slot map)
        #pragma unroll
        for (int it = 0; it < 8; ++it) {
            int idx = it * 256 + tid;
            int d = idx >> 5, f4 = idx & 31;
            float4 v = *(const float4*)(Vtg + (size_t)d * S_DIM + t0 + f4 * 4);
            uint32_t* p = Vs + d * VSTR + (f4 >> 3) * 34 + (f4 & 7) * 4;
            p[0] = f2tf32(v.x); p[1] = f2tf32(v.y); p[2] = f2tf32(v.z); p[3] = f2tf32(v.w);
        }
        __syncthreads();

        // ---- S = Q K^T : warp covers rows r0/r1, all 128 kv cols ----
        float s_acc[16][4] = {};
        #pragma unroll
        for (int k8 = 0; k8 < 8; ++k8) {
            int koff = (k8 >> 2) * 34 + (k8 & 3) * 8 + tg * 2;
            uint2 lo = *(const uint2*)&Qs[r0 * KSTR + koff];
            uint2 hi = *(const uint2*)&Qs[r1 * KSTR + koff];
            uint32_t af[4] = {lo.x, hi.x, lo.y, hi.y};
            #pragma unroll
            for (int nj = 0; nj < 16; ++nj) {
                int col = nj * 8 + gp;
                uint2 bb = *(const uint2*)&Ks[col * KSTR + koff];
                uint32_t bf[2] = {bb.x, bb.y};
                mma_tf32(s_acc[nj], af, bf);
            }
        }

        // ---- register softmax (log2 domain) ----
        float mx0 = -1e30f, mx1 = -1e30f;
        #pragma unroll
        for (int nj = 0; nj < 16; ++nj) {
            mx0 = fmaxf(mx0, fmaxf(s_acc[nj][0], s_acc[nj][1]));
            mx1 = fmaxf(mx1, fmaxf(s_acc[nj][2], s_acc[nj][3]));
        }
        mx0 = fmaxf(mx0, __shfl_xor_sync(0xffffffffu, mx0, 1));
        mx0 = fmaxf(mx0, __shfl_xor_sync(0xffffffffu, mx0, 2));
        mx1 = fmaxf(mx1, __shfl_xor_sync(0xffffffffu, mx1, 1));
        mx1 = fmaxf(mx1, __shfl_xor_sync(0xffffffffu, mx1, 2));
        float m0n = fmaxf(m0, mx0), m1n = fmaxf(m1, mx1);
        float c0 = exp2f(m0 - m0n), c1 = exp2f(m1 - m1n);
        float sum0 = 0.f, sum1 = 0.f;
        #pragma unroll
        for (int nj = 0; nj < 16; ++nj) {
            float p0 = exp2f(s_acc[nj][0] - m0n);
            float p1 = exp2f(s_acc[nj][1] - m0n);
            float p2 = exp2f(s_acc[nj][2] - m1n);
            float p3 = exp2f(s_acc[nj][3] - m1n);
            s_acc[nj][0] = p0; s_acc[nj][1] = p1;
            s_acc[nj][2] = p2; s_acc[nj][3] = p3;
            sum0 += p0 + p1; sum1 += p2 + p3;
        }
        sum0 += __shfl_xor_sync(0xffffffffu, sum0, 1);
        sum0 += __shfl_xor_sync(0xffffffffu, sum0, 2);
        sum1 += __shfl_xor_sync(0xffffffffu, sum1, 1);
        sum1 += __shfl_xor_sync(0xffffffffu, sum1, 2);
        l0 = l0 * c0 + sum0; l1 = l1 * c1 + sum1;
        m0 = m0n; m1 = m1n;
        #pragma unroll
        for (int nj = 0; nj < 8; ++nj) {
            o_acc[nj][0] *= c0; o_acc[nj][1] *= c0;
            o_acc[nj][2] *= c1; o_acc[nj][3] *= c1;
        }

        // ---- O += P V : A-fragments straight from s_acc ----
        #pragma unroll
        for (int k8 = 0; k8 < 16; ++k8) {
            uint32_t af[4] = { f2tf32(s_acc[k8][0]), f2tf32(s_acc[k8][2]),
                               f2tf32(s_acc[k8][1]), f2tf32(s_acc[k8][3]) };
            int koff = (k8 >> 2) * 34 + (k8 & 3) * 8 + tg * 2;
            #pragma unroll
            for (int njd = 0; njd < 8; ++njd) {
                int col = njd * 8 + gp;     // d index
                uint2 bb = *(const uint2*)&Vs[col * VSTR + koff];
                uint32_t bf[2] = {bb.x, bb.y};
                mma_tf32(o_acc[njd], af, bf);
            }
        }
    }

    // ---- epilogue: normalize, stage into Qs (stride KSTR), coalesced store ----
    __syncthreads();
    float* Ds = (float*)Qs;
    float inv0 = 1.f / l0, inv1 = 1.f / l1;
    #pragma unroll
    for (int nj = 0; nj < 8; ++nj) {
        int c = nj * 8 + tg * 2;
        Ds[r0 * KSTR + c]     = o_acc[nj][0] * inv0;
        Ds[r0 * KSTR + c + 1] = o_acc[nj][1] * inv0;
        Ds[r1 * KSTR + c]     = o_acc[nj][2] * inv1;
        Ds[r1 * KSTR + c + 1] = o_acc[nj][3] * inv1;
    }
    __syncthreads();
    float* cb = g_ctx + ((size_t)b * S_DIM + s0) * C_DIM + h * DH;
    #pragma unroll
    for (int it = 0; it < 8; ++it) {
        int idx = it * 256 + tid;
        int r = idx >> 4, c4 = (idx & 15) * 4;
        float4 v = make_float4(Ds[r * KSTR + c4],     Ds[r * KSTR + c4 + 1],
                               Ds[r * KSTR + c4 + 2], Ds[r * KSTR + c4 + 3]);
        *(float4*)(cb + (size_t)r * C_DIM + c4) = v;
    }
}

// ============================================================================
// 5) Output projection (unchanged)
// ============================================================================
__global__ void __launch_bounds__(256) out_mma_kernel(const float* __restrict__ Wo,
                                                      const float* __restrict__ bo,
                                                      float* __restrict__ out) {
    extern __shared__ uint32_t sm[];
    uint32_t* As = sm;
    uint32_t* Bs = sm + 2 * 128 * ASTRIDE;

    int b = blockIdx.z;
    int co0 = blockIdx.y * 128, s0 = blockIdx.x * 128;

    const float* Ag = Wo + (size_t)co0 * C_DIM;
    const float* Bg = g_ctx + ((size_t)b * S_DIM + s0) * C_DIM;

    float acc[4][4][4] = {};
    gemm_mainloop(Ag, Bg, As, Bs, acc);

    float* Ds = (float*)sm;
    stage_D(Ds, acc);
    __syncthreads();

    int tid = threadIdx.x;
    #pragma unroll
    for (int it = 0; it < 16; ++it) {
        int i = it * 256 + tid;
        int s4   = (i & 31) * 4;
        int co_l = i >> 5;
        float bias = bo[co0 + co_l];
        float4 v = make_float4(Ds[co_l * DSTRIDE + s4]     + bias,
                               Ds[co_l * DSTRIDE + s4 + 1] + bias,
                               Ds[co_l * DSTRIDE + s4 + 2] + bias,
                               Ds[co_l * DSTRIDE + s4 + 3] + bias);
        *(float4*)&out[((size_t)b * C_DIM + co0 + co_l) * S_DIM + s0 + s4] = v;
    }
}

// ============================================================================
extern "C" void kernel_launch(void* const* d_in, const int* in_sizes, int n_in,
                              void* d_out, int out_size) {
    const float* x    = (const float*)d_in[0];
    const float* gn_w = (const float*)d_in[1];
    const float* gn_b = (const float*)d_in[2];
    const float* Wq   = (const float*)d_in[3];
    const float* Wk   = (const float*)d_in[4];
    const float* Wv   = (const float*)d_in[5];
    const float* Wo   = (const float*)d_in[6];
    const float* bo   = (const float*)d_in[7];
    float* out = (float*)d_out;

    const int gemm_smem = 4 * 128 * ASTRIDE * (int)sizeof(float);   // 73728 B
    const int attn_smem = (128 * KSTR * 2 + 64 * VSTR) * (int)sizeof(float);  // 105472 B

    gn_stats_kernel<<<B_DIM * GROUPS, 256>>>(x);
    prep_x_kernel<<<dim3(S_DIM / 32, C_DIM / 32, B_DIM), dim3(32, 8)>>>(x, gn_w, gn_b);

    cudaFuncSetAttribute(qkv_mma_kernel, cudaFuncAttributeMaxDynamicSharedMemorySize, gemm_smem);
    qkv_mma_kernel<<<dim3(S_DIM / 128, C_DIM / 128, B_DIM * 3), 256, gemm_smem>>>(Wq, Wk, Wv);

    cudaFuncSetAttribute(attn_mma_kernel, cudaFuncAttributeMaxDynamicSharedMemorySize, attn_smem);
    attn_mma_kernel<<<dim3(S_DIM / 128, B_DIM * N_HEADS), 256, attn_smem>>>();

    cudaFuncSetAttribute(out_mma_kernel, cudaFuncAttributeMaxDynamicSharedMemorySize, gemm_smem);
    out_mma_kernel<<<dim3(S_DIM / 128, C_DIM / 128, B_DIM), 256, gemm_smem>>>(Wo, bo, out);
}

// round 12
// speedup vs baseline: 1.2040x; 1.0646x over previous
#include <cuda_runtime.h>
#include <cstdint>
#include <math.h>

#define B_DIM   8
#define C_DIM   512
#define S_DIM   1024
#define N_HEADS 8
#define DH      64
#define GROUPS  32
#define CPG     16
#define EPS     1e-5f
#define LOG2E   1.4426950408889634f

#define ASTRIDE 36          // gemm smem stage stride (floats) per 32-k row
#define DSTRIDE 133         // gemm smem D-staging stride
#define KSTR    68          // attn Q/K smem row stride (2 chunks of 34)
#define VSTR    140         // attn V smem row stride (4 chunks of 34 + pad)

// ---------------- device scratch (no allocation allowed) ----------------
__device__ float g_mean[B_DIM * GROUPS];
__device__ float g_rstd[B_DIM * GROUPS];
__device__ float g_xT [(size_t)B_DIM * S_DIM * C_DIM];   // [b,s,c] raw
__device__ float g_xnT[(size_t)B_DIM * S_DIM * C_DIM];   // [b,s,c] group-normed
__device__ float g_Q[(size_t)B_DIM * N_HEADS * S_DIM * DH];   // [b,h,s,d]
__device__ float g_K[(size_t)B_DIM * N_HEADS * S_DIM * DH];   // [b,h,s,d]
__device__ float g_V[(size_t)B_DIM * N_HEADS * DH * S_DIM];   // [b,h,d,s]  (transposed)
__device__ float g_ctx[(size_t)B_DIM * S_DIM * C_DIM];   // [b,s,c]

// ---------------- helpers ----------------
__device__ __forceinline__ uint32_t f2tf32(float f) {
    uint32_t r;
    asm("cvt.rna.tf32.f32 %0, %1;" : "=r"(r) : "f"(f));
    return r;
}

__device__ __forceinline__ void mma_tf32(float c[4], const uint32_t a[4], const uint32_t b[2]) {
    asm volatile(
        "mma.sync.aligned.m16n8k8.row.col.f32.tf32.tf32.f32 "
        "{%0,%1,%2,%3},{%4,%5,%6,%7},{%8,%9},{%0,%1,%2,%3};"
        : "+f"(c[0]), "+f"(c[1]), "+f"(c[2]), "+f"(c[3])
        : "r"(a[0]), "r"(a[1]), "r"(a[2]), "r"(a[3]), "r"(b[0]), "r"(b[1]));
}

// ============================================================================
// 1) GroupNorm statistics
// ============================================================================
__global__ void gn_stats_kernel(const float* __restrict__ x) {
    int bg = blockIdx.x;
    const float4* p = (const float4*)(x + (size_t)bg * CPG * S_DIM);
    const int n4 = CPG * S_DIM / 4;
    float s = 0.f, s2 = 0.f;
    for (int i = threadIdx.x; i < n4; i += 256) {
        float4 v = p[i];
        s  += v.x + v.y + v.z + v.w;
        s2 += v.x * v.x + v.y * v.y + v.z * v.z + v.w * v.w;
    }
    __shared__ float ss[256], sq[256];
    ss[threadIdx.x] = s; sq[threadIdx.x] = s2;
    __syncthreads();
    for (int o = 128; o > 0; o >>= 1) {
        if (threadIdx.x < o) { ss[threadIdx.x] += ss[threadIdx.x + o]; sq[threadIdx.x] += sq[threadIdx.x + o]; }
        __syncthreads();
    }
    if (threadIdx.x == 0) {
        const float invN = 1.f / (CPG * S_DIM);
        float mean = ss[0] * invN;
        float var  = sq[0] * invN - mean * mean;
        g_mean[bg] = mean;
        g_rstd[bg] = rsqrtf(var + EPS);
    }
}

// ============================================================================
// 2) x transpose [b,c,s] -> [b,s,c], raw + GroupNormed (fp32)
// ============================================================================
__global__ void prep_x_kernel(const float* __restrict__ x,
                              const float* __restrict__ gw, const float* __restrict__ gb) {
    __shared__ float t[32][33];
    int b = blockIdx.z, s0 = blockIdx.x * 32, c0 = blockIdx.y * 32;
    const float* xb = x + ((size_t)b * C_DIM + c0) * S_DIM + s0;
    #pragma unroll
    for (int j = 0; j < 4; ++j) {
        int c = threadIdx.y + j * 8;
        t[c][threadIdx.x] = xb[(size_t)c * S_DIM + threadIdx.x];
    }
    __syncthreads();
    int c = c0 + threadIdx.x;
    float w = gw[c], bia = gb[c];
    int gi = b * GROUPS + (c >> 4);
    float mu = g_mean[gi], rs = g_rstd[gi];
    #pragma unroll
    for (int j = 0; j < 4; ++j) {
        int s = s0 + threadIdx.y + j * 8;
        float v = t[threadIdx.x][threadIdx.y + j * 8];
        size_t o = ((size_t)b * S_DIM + s) * C_DIM + c;
        g_xT[o]  = v;
        g_xnT[o] = (v - mu) * rs * w + bia;
    }
}

// ============================================================================
// tf32 mma.sync GEMM core (proven R3): D[128,128] = A[128,512]*B[128,512]^T
// ============================================================================
__device__ __forceinline__ void gemm_mainloop(
    const float* __restrict__ Ag, const float* __restrict__ Bg,
    uint32_t* As, uint32_t* Bs, float acc[4][4][4])
{
    const int tid  = threadIdx.x;
    const int lane = tid & 31;
    const int warp = tid >> 5;
    const int my = warp >> 2, wx = warp & 3;
    const int tg = lane & 3, gp = lane >> 2;
    float4 pa[4], pb[4];

#define LDG_STAGE(k0_) do { \
    _Pragma("unroll") \
    for (int it = 0; it < 4; ++it) { \
        int idx = it * 256 + tid; \
        int row = idx >> 3, cq = idx & 7; \
        pa[it] = *(const float4*)(Ag + (size_t)row * C_DIM + (k0_) + cq * 4); \
        pb[it] = *(const float4*)(Bg + (size_t)row * C_DIM + (k0_) + cq * 4); \
    } \
} while (0)

#define STS_STAGE(buf_) do { \
    uint32_t* Ad = As + (buf_) * (128 * ASTRIDE); \
    uint32_t* Bd = Bs + (buf_) * (128 * ASTRIDE); \
    _Pragma("unroll") \
    for (int it = 0; it < 4; ++it) { \
        int idx = it * 256 + tid; \
        int row = idx >> 3, cq = idx & 7; \
        int base = row * ASTRIDE + (cq >> 1) * 8 + (cq & 1); \
        float av[4] = {pa[it].x, pa[it].y, pa[it].z, pa[it].w}; \
        float bv[4] = {pb[it].x, pb[it].y, pb[it].z, pb[it].w}; \
        _Pragma("unroll") \
        for (int j = 0; j < 4; ++j) { \
            Ad[base + 2 * j] = f2tf32(av[j]); \
            Bd[base + 2 * j] = f2tf32(bv[j]); \
        } \
    } \
} while (0)

    LDG_STAGE(0);
    STS_STAGE(0);
    LDG_STAGE(32);
    __syncthreads();

    const int NSTAGE = C_DIM / 32;
    for (int s = 0; s < NSTAGE; ++s) {
        const uint32_t* Ab = As + (s & 1) * (128 * ASTRIDE);
        const uint32_t* Bb = Bs + (s & 1) * (128 * ASTRIDE);
        #pragma unroll
        for (int k8 = 0; k8 < 4; ++k8) {
            uint32_t af[4][4];
            #pragma unroll
            for (int mi = 0; mi < 4; ++mi) {
                int row = my * 64 + mi * 16 + gp;
                uint2 lo = *(const uint2*)&Ab[row * ASTRIDE + k8 * 8 + tg * 2];
                uint2 hi = *(const uint2*)&Ab[(row + 8) * ASTRIDE + k8 * 8 + tg * 2];
                af[mi][0] = lo.x; af[mi][1] = hi.x; af[mi][2] = lo.y; af[mi][3] = hi.y;
            }
            uint32_t bf[4][2];
            #pragma unroll
            for (int nj = 0; nj < 4; ++nj) {
                int col = wx * 32 + nj * 8 + gp;
                uint2 bb = *(const uint2*)&Bb[col * ASTRIDE + k8 * 8 + tg * 2];
                bf[nj][0] = bb.x; bf[nj][1] = bb.y;
            }
            #pragma unroll
            for (int mi = 0; mi < 4; ++mi)
                #pragma unroll
                for (int nj = 0; nj < 4; ++nj)
                    mma_tf32(acc[mi][nj], af[mi], bf[nj]);
        }
        if (s + 1 < NSTAGE) STS_STAGE((s + 1) & 1);
        if (s + 2 < NSTAGE) LDG_STAGE((s + 2) * 32);
        __syncthreads();
    }
#undef LDG_STAGE
#undef STS_STAGE
}

__device__ __forceinline__ void stage_D(float* Ds, const float acc[4][4][4]) {
    const int lane = threadIdx.x & 31;
    const int warp = threadIdx.x >> 5;
    const int my = warp >> 2, wx = warp & 3;
    const int tg = lane & 3, gp = lane >> 2;
    #pragma unroll
    for (int mi = 0; mi < 4; ++mi) {
        int r = my * 64 + mi * 16 + gp;
        #pragma unroll
        for (int nj = 0; nj < 4; ++nj) {
            int c = wx * 32 + nj * 8 + tg * 2;
            Ds[r * DSTRIDE + c]           = acc[mi][nj][0];
            Ds[r * DSTRIDE + c + 1]       = acc[mi][nj][1];
            Ds[(r + 8) * DSTRIDE + c]     = acc[mi][nj][2];
            Ds[(r + 8) * DSTRIDE + c + 1] = acc[mi][nj][3];
        }
    }
}

// ============================================================================
// 3) QKV projection. Q,K stored [b,h,s,d]; V stored transposed [b,h,d,s].
//    launch_bounds (256,2): cap regs at 128 -> 2 CTAs/SM (smem 72KB fits x2)
// ============================================================================
__global__ void __launch_bounds__(256, 2) qkv_mma_kernel(const float* __restrict__ Wq,
                                                         const float* __restrict__ Wk,
                                                         const float* __restrict__ Wv) {
    extern __shared__ uint32_t sm[];
    uint32_t* As = sm;
    uint32_t* Bs = sm + 2 * 128 * ASTRIDE;

    int z = blockIdx.z;
    int mat = z % 3, b = z / 3;
    int co0 = blockIdx.y * 128, s0 = blockIdx.x * 128;

    const float* W  = (mat == 0) ? Wq : (mat == 1) ? Wk : Wv;
    const float* Bt = ((mat == 0) ? g_xnT : g_xT) + (size_t)b * S_DIM * C_DIM;
    const float* Ag = W + (size_t)co0 * C_DIM;
    const float* Bg = Bt + (size_t)s0 * C_DIM;

    float acc[4][4][4] = {};
    gemm_mainloop(Ag, Bg, As, Bs, acc);

    float* Ds = (float*)sm;
    stage_D(Ds, acc);
    __syncthreads();

    int tid = threadIdx.x;
    if (mat == 2) {
        // Vt[b,h,d,s]: rows co_l = (h_l, d), cols = s  (coalesced along s)
        #pragma unroll
        for (int it = 0; it < 16; ++it) {
            int i = it * 256 + tid;
            int s4 = (i & 31) * 4, co_l = i >> 5;
            int h = (co0 >> 6) + (co_l >> 6), d = co_l & 63;
            float4 v = make_float4(Ds[co_l * DSTRIDE + s4],     Ds[co_l * DSTRIDE + s4 + 1],
                                   Ds[co_l * DSTRIDE + s4 + 2], Ds[co_l * DSTRIDE + s4 + 3]);
            *(float4*)&g_V[(((size_t)(b * N_HEADS + h)) * DH + d) * S_DIM + s0 + s4] = v;
        }
    } else {
        float* dst = (mat == 0) ? g_Q : g_K;
        #pragma unroll
        for (int it = 0; it < 16; ++it) {
            int i = it * 256 + tid;
            int d0  = (i & 15) * 4;
            int s_l = (i >> 4) & 127;
            int h_l = i >> 11;
            int row = h_l * 64 + d0;
            float4 v = make_float4(Ds[row * DSTRIDE + s_l],
                                   Ds[(row + 1) * DSTRIDE + s_l],
                                   Ds[(row + 2) * DSTRIDE + s_l],
                                   Ds[(row + 3) * DSTRIDE + s_l]);
            int h = (co0 >> 6) + h_l;
            int s = s0 + s_l;
            *(float4*)&dst[(((size_t)(b * N_HEADS + h)) * S_DIM + s) * DH + d0] = v;
        }
    }
}

// ============================================================================
// 4) Tensor-core flash attention v3.1 (FA2-style, no P smem round trip).
//    Q/K/V all LINEAR in-chunk (group-preserving vs R7 permutation ->
//    S values bit-identical); staging uses 2x STS.64 per float4.
// ============================================================================
__global__ void __launch_bounds__(256, 2) attn_mma_kernel() {
    extern __shared__ float sm_f[];
    uint32_t* Qs = (uint32_t*)sm_f;          // 128 * KSTR
    uint32_t* Ks = Qs + 128 * KSTR;          // 128 * KSTR
    uint32_t* Vs = Ks + 128 * KSTR;          // 64 * VSTR   ([d][kv], linear chunks)

    const int tid = threadIdx.x;
    const int lane = tid & 31, warp = tid >> 5;
    const int tg = lane & 3, gp = lane >> 2;
    const int bh = blockIdx.y;
    const int b = bh >> 3, h = bh & 7;
    const int s0 = blockIdx.x * 128;
    const int r0 = warp * 16 + gp, r1 = r0 + 8;     // this thread's two q-rows

    const float* Qg  = g_Q + (size_t)bh * S_DIM * DH;
    const float* Kg  = g_K + (size_t)bh * S_DIM * DH;
    const float* Vtg = g_V + (size_t)bh * DH * S_DIM;   // [d][s]

    // Q tile: tf32, linear in-chunk, scaled by 1/8 * log2(e)
    const float qscale = 0.125f * LOG2E;
    #pragma unroll
    for (int it = 0; it < 8; ++it) {
        int idx = it * 256 + tid;
        int row = idx >> 4, f4 = idx & 15;
        float4 v = *(const float4*)(Qg + (size_t)(s0 + row) * DH + f4 * 4);
        uint32_t* p = Qs + row * KSTR + (f4 >> 3) * 34 + (f4 & 7) * 4;
        *(uint2*)(p)     = make_uint2(f2tf32(v.x * qscale), f2tf32(v.y * qscale));
        *(uint2*)(p + 2) = make_uint2(f2tf32(v.z * qscale), f2tf32(v.w * qscale));
    }

    float m0 = -1e30f, m1 = -1e30f, l0 = 0.f, l1 = 0.f;
    float o_acc[8][4] = {};

    for (int t0 = 0; t0 < S_DIM; t0 += 128) {
        __syncthreads();   // prev PV reads of Ks/Vs done (iter0: Qs visible)
        // K tile [kv=128][d=64], linear in-chunk
        #pragma unroll
        for (int it = 0; it < 8; ++it) {
            int idx = it * 256 + tid;
            int row = idx >> 4, f4 = idx & 15;
            float4 v = *(const float4*)(Kg + (size_t)(t0 + row) * DH + f4 * 4);
            uint32_t* p = Ks + row * KSTR + (f4 >> 3) * 34 + (f4 & 7) * 4;
            *(uint2*)(p)     = make_uint2(f2tf32(v.x), f2tf32(v.y));
            *(uint2*)(p + 2) = make_uint2(f2tf32(v.z), f2tf32(v.w));
        }
        // V tile [d=64][kv=128], linear in-chunk
        #pragma unroll
        for (int it = 0; it < 8; ++it) {
            int idx = it * 256 + tid;
            int d = idx >> 5, f4 = idx & 31;
            float4 v = *(const float4*)(Vtg + (size_t)d * S_DIM + t0 + f4 * 4);
            uint32_t* p = Vs + d * VSTR + (f4 >> 3) * 34 + (f4 & 7) * 4;
            *(uint2*)(p)     = make_uint2(f2tf32(v.x), f2tf32(v.y));
            *(uint2*)(p + 2) = make_uint2(f2tf32(v.z), f2tf32(v.w));
        }
        __syncthreads();

        // ---- S = Q K^T : warp covers rows r0/r1, all 128 kv cols ----
        float s_acc[16][4] = {};
        #pragma unroll
        for (int k8 = 0; k8 < 8; ++k8) {
            int koff = (k8 >> 2) * 34 + (k8 & 3) * 8 + tg * 2;
            uint2 lo = *(const uint2*)&Qs[r0 * KSTR + koff];
            uint2 hi = *(const uint2*)&Qs[r1 * KSTR + koff];
            uint32_t af[4] = {lo.x, hi.x, lo.y, hi.y};
            #pragma unroll
            for (int nj = 0; nj < 16; ++nj) {
                int col = nj * 8 + gp;
                uint2 bb = *(const uint2*)&Ks[col * KSTR + koff];
                uint32_t bf[2] = {bb.x, bb.y};
                mma_tf32(s_acc[nj], af, bf);
            }
        }

        // ---- register softmax (log2 domain) ----
        float mx0 = -1e30f, mx1 = -1e30f;
        #pragma unroll
        for (int nj = 0; nj < 16; ++nj) {
            mx0 = fmaxf(mx0, fmaxf(s_acc[nj][0], s_acc[nj][1]));
            mx1 = fmaxf(mx1, fmaxf(s_acc[nj][2], s_acc[nj][3]));
        }
        mx0 = fmaxf(mx0, __shfl_xor_sync(0xffffffffu, mx0, 1));
        mx0 = fmaxf(mx0, __shfl_xor_sync(0xffffffffu, mx0, 2));
        mx1 = fmaxf(mx1, __shfl_xor_sync(0xffffffffu, mx1, 1));
        mx1 = fmaxf(mx1, __shfl_xor_sync(0xffffffffu, mx1, 2));
        float m0n = fmaxf(m0, mx0), m1n = fmaxf(m1, mx1);
        float c0 = exp2f(m0 - m0n), c1 = exp2f(m1 - m1n);
        float sum0 = 0.f, sum1 = 0.f;
        #pragma unroll
        for (int nj = 0; nj < 16; ++nj) {
            float p0 = exp2f(s_acc[nj][0] - m0n);
            float p1 = exp2f(s_acc[nj][1] - m0n);
            float p2 = exp2f(s_acc[nj][2] - m1n);
            float p3 = exp2f(s_acc[nj][3] - m1n);
            s_acc[nj][0] = p0; s_acc[nj][1] = p1;
            s_acc[nj][2] = p2; s_acc[nj][3] = p3;
            sum0 += p0 + p1; sum1 += p2 + p3;
        }
        sum0 += __shfl_xor_sync(0xffffffffu, sum0, 1);
        sum0 += __shfl_xor_sync(0xffffffffu, sum0, 2);
        sum1 += __shfl_xor_sync(0xffffffffu, sum1, 1);
        sum1 += __shfl_xor_sync(0xffffffffu, sum1, 2);
        l0 = l0 * c0 + sum0; l1 = l1 * c1 + sum1;
        m0 = m0n; m1 = m1n;
        #pragma unroll
        for (int nj = 0; nj < 8; ++nj) {
            o_acc[nj][0] *= c0; o_acc[nj][1] *= c0;
            o_acc[nj][2] *= c1; o_acc[nj][3] *= c1;
        }

        // ---- O += P V : A-fragments straight from s_acc ----
        #pragma unroll
        for (int k8 = 0; k8 < 16; ++k8) {
            uint32_t af[4] = { f2tf32(s_acc[k8][0]), f2tf32(s_acc[k8][2]),
                               f2tf32(s_acc[k8][1]), f2tf32(s_acc[k8][3]) };
            int koff = (k8 >> 2) * 34 + (k8 & 3) * 8 + tg * 2;
            #pragma unroll
            for (int njd = 0; njd < 8; ++njd) {
                int col = njd * 8 + gp;     // d index
                uint2 bb = *(const uint2*)&Vs[col * VSTR + koff];
                uint32_t bf[2] = {bb.x, bb.y};
                mma_tf32(o_acc[njd], af, bf);
            }
        }
    }

    // ---- epilogue: normalize, stage into Qs (stride KSTR), coalesced store ----
    __syncthreads();
    float* Ds = (float*)Qs;
    float inv0 = 1.f / l0, inv1 = 1.f / l1;
    #pragma unroll
    for (int nj = 0; nj < 8; ++nj) {
        int c = nj * 8 + tg * 2;
        Ds[r0 * KSTR + c]     = o_acc[nj][0] * inv0;
        Ds[r0 * KSTR + c + 1] = o_acc[nj][1] * inv0;
        Ds[r1 * KSTR + c]     = o_acc[nj][2] * inv1;
        Ds[r1 * KSTR + c + 1] = o_acc[nj][3] * inv1;
    }
    __syncthreads();
    float* cb = g_ctx + ((size_t)b * S_DIM + s0) * C_DIM + h * DH;
    #pragma unroll
    for (int it = 0; it < 8; ++it) {
        int idx = it * 256 + tid;
        int r = idx >> 4, c4 = (idx & 15) * 4;
        float4 v = make_float4(Ds[r * KSTR + c4],     Ds[r * KSTR + c4 + 1],
                               Ds[r * KSTR + c4 + 2], Ds[r * KSTR + c4 + 3]);
        *(float4*)(cb + (size_t)r * C_DIM + c4) = v;
    }
}

// ============================================================================
// 5) Output projection ((256,2) for 2 CTAs/SM)
// ============================================================================
__global__ void __launch_bounds__(256, 2) out_mma_kernel(const float* __restrict__ Wo,
                                                         const float* __restrict__ bo,
                                                         float* __restrict__ out) {
    extern __shared__ uint32_t sm[];
    uint32_t* As = sm;
    uint32_t* Bs = sm + 2 * 128 * ASTRIDE;

    int b = blockIdx.z;
    int co0 = blockIdx.y * 128, s0 = blockIdx.x * 128;

    const float* Ag = Wo + (size_t)co0 * C_DIM;
    const float* Bg = g_ctx + ((size_t)b * S_DIM + s0) * C_DIM;

    float acc[4][4][4] = {};
    gemm_mainloop(Ag, Bg, As, Bs, acc);

    float* Ds = (float*)sm;
    stage_D(Ds, acc);
    __syncthreads();

    int tid = threadIdx.x;
    #pragma unroll
    for (int it = 0; it < 16; ++it) {
        int i = it * 256 + tid;
        int s4   = (i & 31) * 4;
        int co_l = i >> 5;
        float bias = bo[co0 + co_l];
        float4 v = make_float4(Ds[co_l * DSTRIDE + s4]     + bias,
                               Ds[co_l * DSTRIDE + s4 + 1] + bias,
                               Ds[co_l * DSTRIDE + s4 + 2] + bias,
                               Ds[co_l * DSTRIDE + s4 + 3] + bias);
        *(float4*)&out[((size_t)b * C_DIM + co0 + co_l) * S_DIM + s0 + s4] = v;
    }
}

// ============================================================================
extern "C" void kernel_launch(void* const* d_in, const int* in_sizes, int n_in,
                              void* d_out, int out_size) {
    const float* x    = (const float*)d_in[0];
    const float* gn_w = (const float*)d_in[1];
    const float* gn_b = (const float*)d_in[2];
    const float* Wq   = (const float*)d_in[3];
    const float* Wk   = (const float*)d_in[4];
    const float* Wv   = (const float*)d_in[5];
    const float* Wo   = (const float*)d_in[6];
    const float* bo   = (const float*)d_in[7];
    float* out = (float*)d_out;

    const int gemm_smem = 4 * 128 * ASTRIDE * (int)sizeof(float);   // 73728 B
    const int attn_smem = (128 * KSTR * 2 + 64 * VSTR) * (int)sizeof(float);  // 105472 B

    gn_stats_kernel<<<B_DIM * GROUPS, 256>>>(x);
    prep_x_kernel<<<dim3(S_DIM / 32, C_DIM / 32, B_DIM), dim3(32, 8)>>>(x, gn_w, gn_b);

    cudaFuncSetAttribute(qkv_mma_kernel, cudaFuncAttributeMaxDynamicSharedMemorySize, gemm_smem);
    qkv_mma_kernel<<<dim3(S_DIM / 128, C_DIM / 128, B_DIM * 3), 256, gemm_smem>>>(Wq, Wk, Wv);

    cudaFuncSetAttribute(attn_mma_kernel, cudaFuncAttributeMaxDynamicSharedMemorySize, attn_smem);
    attn_mma_kernel<<<dim3(S_DIM / 128, B_DIM * N_HEADS), 256, attn_smem>>>();

    cudaFuncSetAttribute(out_mma_kernel, cudaFuncAttributeMaxDynamicSharedMemorySize, gemm_smem);
    out_mma_kernel<<<dim3(S_DIM / 128, C_DIM / 128, B_DIM), 256, gemm_smem>>>(Wo, bo, out);
}

// round 15
// speedup vs baseline: 1.2106x; 1.0054x over previous
#include <cuda_runtime.h>
#include <cstdint>
#include <math.h>

#define B_DIM   8
#define C_DIM   512
#define S_DIM   1024
#define N_HEADS 8
#define DH      64
#define GROUPS  32
#define CPG     16
#define EPS     1e-5f
#define LOG2E   1.4426950408889634f

#define ASTRIDE 36          // gemm smem stage stride (floats) per 32-k row
#define DSTRIDE 133         // gemm smem D-staging stride
#define KSTR    68          // attn Q/K smem row stride (2 chunks of 34)
#define VSTR    140         // attn V smem row stride (4 chunks of 34 + pad)
#define QTILE   256         // attn q-tile rows (16 warps x 16 rows)

// ---------------- device scratch (no allocation allowed) ----------------
__device__ float g_mean[B_DIM * GROUPS];
__device__ float g_rstd[B_DIM * GROUPS];
__device__ float g_xT [(size_t)B_DIM * S_DIM * C_DIM];   // [b,s,c] raw
__device__ float g_xnT[(size_t)B_DIM * S_DIM * C_DIM];   // [b,s,c] group-normed
__device__ float g_Q[(size_t)B_DIM * N_HEADS * S_DIM * DH];   // [b,h,s,d]
__device__ float g_K[(size_t)B_DIM * N_HEADS * S_DIM * DH];   // [b,h,s,d]
__device__ float g_V[(size_t)B_DIM * N_HEADS * DH * S_DIM];   // [b,h,d,s]  (transposed)
__device__ float g_ctx[(size_t)B_DIM * S_DIM * C_DIM];   // [b,s,c]

// ---------------- helpers ----------------
__device__ __forceinline__ uint32_t f2tf32(float f) {
    uint32_t r;
    asm("cvt.rna.tf32.f32 %0, %1;" : "=r"(r) : "f"(f));
    return r;
}

__device__ __forceinline__ void mma_tf32(float c[4], const uint32_t a[4], const uint32_t b[2]) {
    asm volatile(
        "mma.sync.aligned.m16n8k8.row.col.f32.tf32.tf32.f32 "
        "{%0,%1,%2,%3},{%4,%5,%6,%7},{%8,%9},{%0,%1,%2,%3};"
        : "+f"(c[0]), "+f"(c[1]), "+f"(c[2]), "+f"(c[3])
        : "r"(a[0]), "r"(a[1]), "r"(a[2]), "r"(a[3]), "r"(b[0]), "r"(b[1]));
}

// ============================================================================
// 1) GroupNorm statistics
// ============================================================================
__global__ void gn_stats_kernel(const float* __restrict__ x) {
    int bg = blockIdx.x;
    const float4* p = (const float4*)(x + (size_t)bg * CPG * S_DIM);
    const int n4 = CPG * S_DIM / 4;
    float s = 0.f, s2 = 0.f;
    for (int i = threadIdx.x; i < n4; i += 256) {
        float4 v = p[i];
        s  += v.x + v.y + v.z + v.w;
        s2 += v.x * v.x + v.y * v.y + v.z * v.z + v.w * v.w;
    }
    __shared__ float ss[256], sq[256];
    ss[threadIdx.x] = s; sq[threadIdx.x] = s2;
    __syncthreads();
    for (int o = 128; o > 0; o >>= 1) {
        if (threadIdx.x < o) { ss[threadIdx.x] += ss[threadIdx.x + o]; sq[threadIdx.x] += sq[threadIdx.x + o]; }
        __syncthreads();
    }
    if (threadIdx.x == 0) {
        const float invN = 1.f / (CPG * S_DIM);
        float mean = ss[0] * invN;
        float var  = sq[0] * invN - mean * mean;
        g_mean[bg] = mean;
        g_rstd[bg] = rsqrtf(var + EPS);
    }
}

// ============================================================================
// 2) x transpose [b,c,s] -> [b,s,c], raw + GroupNormed (fp32)
// ============================================================================
__global__ void prep_x_kernel(const float* __restrict__ x,
                              const float* __restrict__ gw, const float* __restrict__ gb) {
    __shared__ float t[32][33];
    int b = blockIdx.z, s0 = blockIdx.x * 32, c0 = blockIdx.y * 32;
    const float* xb = x + ((size_t)b * C_DIM + c0) * S_DIM + s0;
    #pragma unroll
    for (int j = 0; j < 4; ++j) {
        int c = threadIdx.y + j * 8;
        t[c][threadIdx.x] = xb[(size_t)c * S_DIM + threadIdx.x];
    }
    __syncthreads();
    int c = c0 + threadIdx.x;
    float w = gw[c], bia = gb[c];
    int gi = b * GROUPS + (c >> 4);
    float mu = g_mean[gi], rs = g_rstd[gi];
    #pragma unroll
    for (int j = 0; j < 4; ++j) {
        int s = s0 + threadIdx.y + j * 8;
        float v = t[threadIdx.x][threadIdx.y + j * 8];
        size_t o = ((size_t)b * S_DIM + s) * C_DIM + c;
        g_xT[o]  = v;
        g_xnT[o] = (v - mu) * rs * w + bia;
    }
}

// ============================================================================
// tf32 mma.sync GEMM core (proven R3): D[128,128] = A[128,512]*B[128,512]^T
// ============================================================================
__device__ __forceinline__ void gemm_mainloop(
    const float* __restrict__ Ag, const float* __restrict__ Bg,
    uint32_t* As, uint32_t* Bs, float acc[4][4][4])
{
    const int tid  = threadIdx.x;
    const int lane = tid & 31;
    const int warp = tid >> 5;
    const int my = warp >> 2, wx = warp & 3;
    const int tg = lane & 3, gp = lane >> 2;
    float4 pa[4], pb[4];

#define LDG_STAGE(k0_) do { \
    _Pragma("unroll") \
    for (int it = 0; it < 4; ++it) { \
        int idx = it * 256 + tid; \
        int row = idx >> 3, cq = idx & 7; \
        pa[it] = *(const float4*)(Ag + (size_t)row * C_DIM + (k0_) + cq * 4); \
        pb[it] = *(const float4*)(Bg + (size_t)row * C_DIM + (k0_) + cq * 4); \
    } \
} while (0)

#define STS_STAGE(buf_) do { \
    uint32_t* Ad = As + (buf_) * (128 * ASTRIDE); \
    uint32_t* Bd = Bs + (buf_) * (128 * ASTRIDE); \
    _Pragma("unroll") \
    for (int it = 0; it < 4; ++it) { \
        int idx = it * 256 + tid; \
        int row = idx >> 3, cq = idx & 7; \
        int base = row * ASTRIDE + (cq >> 1) * 8 + (cq & 1); \
        float av[4] = {pa[it].x, pa[it].y, pa[it].z, pa[it].w}; \
        float bv[4] = {pb[it].x, pb[it].y, pb[it].z, pb[it].w}; \
        _Pragma("unroll") \
        for (int j = 0; j < 4; ++j) { \
            Ad[base + 2 * j] = f2tf32(av[j]); \
            Bd[base + 2 * j] = f2tf32(bv[j]); \
        } \
    } \
} while (0)

    LDG_STAGE(0);
    STS_STAGE(0);
    LDG_STAGE(32);
    __syncthreads();

    const int NSTAGE = C_DIM / 32;
    for (int s = 0; s < NSTAGE; ++s) {
        const uint32_t* Ab = As + (s & 1) * (128 * ASTRIDE);
        const uint32_t* Bb = Bs + (s & 1) * (128 * ASTRIDE);
        #pragma unroll
        for (int k8 = 0; k8 < 4; ++k8) {
            uint32_t af[4][4];
            #pragma unroll
            for (int mi = 0; mi < 4; ++mi) {
                int row = my * 64 + mi * 16 + gp;
                uint2 lo = *(const uint2*)&Ab[row * ASTRIDE + k8 * 8 + tg * 2];
                uint2 hi = *(const uint2*)&Ab[(row + 8) * ASTRIDE + k8 * 8 + tg * 2];
                af[mi][0] = lo.x; af[mi][1] = hi.x; af[mi][2] = lo.y; af[mi][3] = hi.y;
            }
            uint32_t bf[4][2];
            #pragma unroll
            for (int nj = 0; nj < 4; ++nj) {
                int col = wx * 32 + nj * 8 + gp;
                uint2 bb = *(const uint2*)&Bb[col * ASTRIDE + k8 * 8 + tg * 2];
                bf[nj][0] = bb.x; bf[nj][1] = bb.y;
            }
            #pragma unroll
            for (int mi = 0; mi < 4; ++mi)
                #pragma unroll
                for (int nj = 0; nj < 4; ++nj)
                    mma_tf32(acc[mi][nj], af[mi], bf[nj]);
        }
        if (s + 1 < NSTAGE) STS_STAGE((s + 1) & 1);
        if (s + 2 < NSTAGE) LDG_STAGE((s + 2) * 32);
        __syncthreads();
    }
#undef LDG_STAGE
#undef STS_STAGE
}

__device__ __forceinline__ void stage_D(float* Ds, const float acc[4][4][4]) {
    const int lane = threadIdx.x & 31;
    const int warp = threadIdx.x >> 5;
    const int my = warp >> 2, wx = warp & 3;
    const int tg = lane & 3, gp = lane >> 2;
    #pragma unroll
    for (int mi = 0; mi < 4; ++mi) {
        int r = my * 64 + mi * 16 + gp;
        #pragma unroll
        for (int nj = 0; nj < 4; ++nj) {
            int c = wx * 32 + nj * 8 + tg * 2;
            Ds[r * DSTRIDE + c]           = acc[mi][nj][0];
            Ds[r * DSTRIDE + c + 1]       = acc[mi][nj][1];
            Ds[(r + 8) * DSTRIDE + c]     = acc[mi][nj][2];
            Ds[(r + 8) * DSTRIDE + c + 1] = acc[mi][nj][3];
        }
    }
}

// ============================================================================
// 3) QKV projection. Q,K stored [b,h,s,d]; V stored transposed [b,h,d,s].
// ============================================================================
__global__ void __launch_bounds__(256, 2) qkv_mma_kernel(const float* __restrict__ Wq,
                                                         const float* __restrict__ Wk,
                                                         const float* __restrict__ Wv) {
    extern __shared__ uint32_t sm[];
    uint32_t* As = sm;
    uint32_t* Bs = sm + 2 * 128 * ASTRIDE;

    int z = blockIdx.z;
    int mat = z % 3, b = z / 3;
    int co0 = blockIdx.y * 128, s0 = blockIdx.x * 128;

    const float* W  = (mat == 0) ? Wq : (mat == 1) ? Wk : Wv;
    const float* Bt = ((mat == 0) ? g_xnT : g_xT) + (size_t)b * S_DIM * C_DIM;
    const float* Ag = W + (size_t)co0 * C_DIM;
    const float* Bg = Bt + (size_t)s0 * C_DIM;

    float acc[4][4][4] = {};
    gemm_mainloop(Ag, Bg, As, Bs, acc);

    float* Ds = (float*)sm;
    stage_D(Ds, acc);
    __syncthreads();

    int tid = threadIdx.x;
    if (mat == 2) {
        // Vt[b,h,d,s]: rows co_l = (h_l, d), cols = s  (coalesced along s)
        #pragma unroll
        for (int it = 0; it < 16; ++it) {
            int i = it * 256 + tid;
            int s4 = (i & 31) * 4, co_l = i >> 5;
            int h = (co0 >> 6) + (co_l >> 6), d = co_l & 63;
            float4 v = make_float4(Ds[co_l * DSTRIDE + s4],     Ds[co_l * DSTRIDE + s4 + 1],
                                   Ds[co_l * DSTRIDE + s4 + 2], Ds[co_l * DSTRIDE + s4 + 3]);
            *(float4*)&g_V[(((size_t)(b * N_HEADS + h)) * DH + d) * S_DIM + s0 + s4] = v;
        }
    } else {
        float* dst = (mat == 0) ? g_Q : g_K;
        #pragma unroll
        for (int it = 0; it < 16; ++it) {
            int i = it * 256 + tid;
            int d0  = (i & 15) * 4;
            int s_l = (i >> 4) & 127;
            int h_l = i >> 11;
            int row = h_l * 64 + d0;
            float4 v = make_float4(Ds[row * DSTRIDE + s_l],
                                   Ds[(row + 1) * DSTRIDE + s_l],
                                   Ds[(row + 2) * DSTRIDE + s_l],
                                   Ds[(row + 3) * DSTRIDE + s_l]);
            int h = (co0 >> 6) + h_l;
            int s = s0 + s_l;
            *(float4*)&dst[(((size_t)(b * N_HEADS + h)) * S_DIM + s) * DH + d0] = v;
        }
    }
}

// ============================================================================
// 4) Tensor-core flash attention v4: q-tile 256, kv-tile 128, 16 warps,
//    1 CTA/SM. Each staged K/V tile amortized over 2x the q-rows vs v3.1;
//    per-warp structure (16 q-rows, register softmax, direct P feed) identical.
// ============================================================================
__global__ void __launch_bounds__(512, 1) attn_mma_kernel() {
    extern __shared__ float sm_f[];
    uint32_t* Qs = (uint32_t*)sm_f;          // QTILE * KSTR
    uint32_t* Ks = Qs + QTILE * KSTR;        // 128 * KSTR
    uint32_t* Vs = Ks + 128 * KSTR;          // 64 * VSTR   ([d][kv], linear chunks)

    const int tid = threadIdx.x;
    const int lane = tid & 31, warp = tid >> 5;     // warp 0..15
    const int tg = lane & 3, gp = lane >> 2;
    const int bh = blockIdx.y;
    const int b = bh >> 3, h = bh & 7;
    const int s0 = blockIdx.x * QTILE;
    const int r0 = warp * 16 + gp, r1 = r0 + 8;     // this thread's two q-rows

    const float* Qg  = g_Q + (size_t)bh * S_DIM * DH;
    const float* Kg  = g_K + (size_t)bh * S_DIM * DH;
    const float* Vtg = g_V + (size_t)bh * DH * S_DIM;   // [d][s]

    // Q tile: tf32, linear in-chunk, scaled by 1/8 * log2(e)
    const float qscale = 0.125f * LOG2E;
    #pragma unroll
    for (int it = 0; it < 8; ++it) {
        int idx = it * 512 + tid;
        int row = idx >> 4, f4 = idx & 15;
        float4 v = *(const float4*)(Qg + (size_t)(s0 + row) * DH + f4 * 4);
        uint32_t* p = Qs + row * KSTR + (f4 >> 3) * 34 + (f4 & 7) * 4;
        *(uint2*)(p)     = make_uint2(f2tf32(v.x * qscale), f2tf32(v.y * qscale));
        *(uint2*)(p + 2) = make_uint2(f2tf32(v.z * qscale), f2tf32(v.w * qscale));
    }

    float m0 = -1e30f, m1 = -1e30f, l0 = 0.f, l1 = 0.f;
    float o_acc[8][4] = {};

    for (int t0 = 0; t0 < S_DIM; t0 += 128) {
        __syncthreads();   // prev PV reads of Ks/Vs done (iter0: Qs visible)
        // K tile [kv=128][d=64], linear in-chunk
        #pragma unroll
        for (int it = 0; it < 4; ++it) {
            int idx = it * 512 + tid;
            int row = idx >> 4, f4 = idx & 15;
            float4 v = *(const float4*)(Kg + (size_t)(t0 + row) * DH + f4 * 4);
            uint32_t* p = Ks + row * KSTR + (f4 >> 3) * 34 + (f4 & 7) * 4;
            *(uint2*)(p)     = make_uint2(f2tf32(v.x), f2tf32(v.y));
            *(uint2*)(p + 2) = make_uint2(f2tf32(v.z), f2tf32(v.w));
        }
        // V tile [d=64][kv=128], linear in-chunk
        #pragma unroll
        for (int it = 0; it < 4; ++it) {
            int idx = it * 512 + tid;
            int d = idx >> 5, f4 = idx & 31;
            float4 v = *(const float4*)(Vtg + (size_t)d * S_DIM + t0 + f4 * 4);
            uint32_t* p = Vs + d * VSTR + (f4 >> 3) * 34 + (f4 & 7) * 4;
            *(uint2*)(p)     = make_uint2(f2tf32(v.x), f2tf32(v.y));
            *(uint2*)(p + 2) = make_uint2(f2tf32(v.z), f2tf32(v.w));
        }
        __syncthreads();

        // ---- S = Q K^T : warp covers rows r0/r1, all 128 kv cols ----
        float s_acc[16][4] = {};
        #pragma unroll
        for (int k8 = 0; k8 < 8; ++k8) {
            int koff = (k8 >> 2) * 34 + (k8 & 3) * 8 + tg * 2;
            uint2 lo = *(const uint2*)&Qs[r0 * KSTR + koff];
            uint2 hi = *(const uint2*)&Qs[r1 * KSTR + koff];
            uint32_t af[4] = {lo.x, hi.x, lo.y, hi.y};
            #pragma unroll
            for (int nj = 0; nj < 16; ++nj) {
                int col = nj * 8 + gp;
                uint2 bb = *(const uint2*)&Ks[col * KSTR + koff];
                uint32_t bf[2] = {bb.x, bb.y};
                mma_tf32(s_acc[nj], af, bf);
            }
        }

        // ---- register softmax (log2 domain) ----
        float mx0 = -1e30f, mx1 = -1e30f;
        #pragma unroll
        for (int nj = 0; nj < 16; ++nj) {
            mx0 = fmaxf(mx0, fmaxf(s_acc[nj][0], s_acc[nj][1]));
            mx1 = fmaxf(mx1, fmaxf(s_acc[nj][2], s_acc[nj][3]));
        }
        mx0 = fmaxf(mx0, __shfl_xor_sync(0xffffffffu, mx0, 1));
        mx0 = fmaxf(mx0, __shfl_xor_sync(0xffffffffu, mx0, 2));
        mx1 = fmaxf(mx1, __shfl_xor_sync(0xffffffffu, mx1, 1));
        mx1 = fmaxf(mx1, __shfl_xor_sync(0xffffffffu, mx1, 2));
        float m0n = fmaxf(m0, mx0), m1n = fmaxf(m1, mx1);
        float c0 = exp2f(m0 - m0n), c1 = exp2f(m1 - m1n);
        float sum0 = 0.f, sum1 = 0.f;
        #pragma unroll
        for (int nj = 0; nj < 16; ++nj) {
            float p0 = exp2f(s_acc[nj][0] - m0n);
            float p1 = exp2f(s_acc[nj][1] - m0n);
            float p2 = exp2f(s_acc[nj][2] - m1n);
            float p3 = exp2f(s_acc[nj][3] - m1n);
            s_acc[nj][0] = p0; s_acc[nj][1] = p1;
            s_acc[nj][2] = p2; s_acc[nj][3] = p3;
            sum0 += p0 + p1; sum1 += p2 + p3;
        }
        sum0 += __shfl_xor_sync(0xffffffffu, sum0, 1);
        sum0 += __shfl_xor_sync(0xffffffffu, sum0, 2);
        sum1 += __shfl_xor_sync(0xffffffffu, sum1, 1);
        sum1 += __shfl_xor_sync(0xffffffffu, sum1, 2);
        l0 = l0 * c0 + sum0; l1 = l1 * c1 + sum1;
        m0 = m0n; m1 = m1n;
        #pragma unroll
        for (int nj = 0; nj < 8; ++nj) {
            o_acc[nj][0] *= c0; o_acc[nj][1] *= c0;
            o_acc[nj][2] *= c1; o_acc[nj][3] *= c1;
        }

        // ---- O += P V : A-fragments straight from s_acc ----
        #pragma unroll
        for (int k8 = 0; k8 < 16; ++k8) {
            uint32_t af[4] = { f2tf32(s_acc[k8][0]), f2tf32(s_acc[k8][2]),
                               f2tf32(s_acc[k8][1]), f2tf32(s_acc[k8][3]) };
            int koff = (k8 >> 2) * 34 + (k8 & 3) * 8 + tg * 2;
            #pragma unroll
            for (int njd = 0; njd < 8; ++njd) {
                int col = njd * 8 + gp;     // d index
                uint2 bb = *(const uint2*)&Vs[col * VSTR + koff];
                uint32_t bf[2] = {bb.x, bb.y};
                mma_tf32(o_acc[njd], af, bf);
            }
        }
    }

    // ---- epilogue: normalize, stage into Qs (stride KSTR), coalesced store ----
    __syncthreads();
    float* Ds = (float*)Qs;
    float inv0 = 1.f / l0, inv1 = 1.f / l1;
    #pragma unroll
    for (int nj = 0; nj < 8; ++nj) {
        int c = nj * 8 + tg * 2;
        Ds[r0 * KSTR + c]     = o_acc[nj][0] * inv0;
        Ds[r0 * KSTR + c + 1] = o_acc[nj][1] * inv0;
        Ds[r1 * KSTR + c]     = o_acc[nj][2] * inv1;
        Ds[r1 * KSTR + c + 1] = o_acc[nj][3] * inv1;
    }
    __syncthreads();
    float* cb = g_ctx + ((size_t)b * S_DIM + s0) * C_DIM + h * DH;
    #pragma unroll
    for (int it = 0; it < 8; ++it) {
        int idx = it * 512 + tid;
        int r = idx >> 4, c4 = (idx & 15) * 4;
        float4 v = make_float4(Ds[r * KSTR + c4],     Ds[r * KSTR + c4 + 1],
                               Ds[r * KSTR + c4 + 2], Ds[r * KSTR + c4 + 3]);
        *(float4*)(cb + (size_t)r * C_DIM + c4) = v;
    }
}

// ============================================================================
// 5) Output projection ((256,2) for 2 CTAs/SM)
// ============================================================================
__global__ void __launch_bounds__(256, 2) out_mma_kernel(const float* __restrict__ Wo,
                                                         const float* __restrict__ bo,
                                                         float* __restrict__ out) {
    extern __shared__ uint32_t sm[];
    uint32_t* As = sm;
    uint32_t* Bs = sm + 2 * 128 * ASTRIDE;

    int b = blockIdx.z;
    int co0 = blockIdx.y * 128, s0 = blockIdx.x * 128;

    const float* Ag = Wo + (size_t)co0 * C_DIM;
    const float* Bg = g_ctx + ((size_t)b * S_DIM + s0) * C_DIM;

    float acc[4][4][4] = {};
    gemm_mainloop(Ag, Bg, As, Bs, acc);

    float* Ds = (float*)sm;
    stage_D(Ds, acc);
    __syncthreads();

    int tid = threadIdx.x;
    #pragma unroll
    for (int it = 0; it < 16; ++it) {
        int i = it * 256 + tid;
        int s4   = (i & 31) * 4;
        int co_l = i >> 5;
        float bias = bo[co0 + co_l];
        float4 v = make_float4(Ds[co_l * DSTRIDE + s4]     + bias,
                               Ds[co_l * DSTRIDE + s4 + 1] + bias,
                               Ds[co_l * DSTRIDE + s4 + 2] + bias,
                               Ds[co_l * DSTRIDE + s4 + 3] + bias);
        *(float4*)&out[((size_t)b * C_DIM + co0 + co_l) * S_DIM + s0 + s4] = v;
    }
}

// ============================================================================
extern "C" void kernel_launch(void* const* d_in, const int* in_sizes, int n_in,
                              void* d_out, int out_size) {
    const float* x    = (const float*)d_in[0];
    const float* gn_w = (const float*)d_in[1];
    const float* gn_b = (const float*)d_in[2];
    const float* Wq   = (const float*)d_in[3];
    const float* Wk   = (const float*)d_in[4];
    const float* Wv   = (const float*)d_in[5];
    const float* Wo   = (const float*)d_in[6];
    const float* bo   = (const float*)d_in[7];
    float* out = (float*)d_out;

    const int gemm_smem = 4 * 128 * ASTRIDE * (int)sizeof(float);   // 73728 B
    const int attn_smem = (QTILE * KSTR + 128 * KSTR + 64 * VSTR)
                          * (int)sizeof(float);                     // 140288 B

    gn_stats_kernel<<<B_DIM * GROUPS, 256>>>(x);
    prep_x_kernel<<<dim3(S_DIM / 32, C_DIM / 32, B_DIM), dim3(32, 8)>>>(x, gn_w, gn_b);

    cudaFuncSetAttribute(qkv_mma_kernel, cudaFuncAttributeMaxDynamicSharedMemorySize, gemm_smem);
    qkv_mma_kernel<<<dim3(S_DIM / 128, C_DIM / 128, B_DIM * 3), 256, gemm_smem>>>(Wq, Wk, Wv);

    cudaFuncSetAttribute(attn_mma_kernel, cudaFuncAttributeMaxDynamicSharedMemorySize, attn_smem);
    attn_mma_kernel<<<dim3(S_DIM / QTILE, B_DIM * N_HEADS), 512, attn_smem>>>();

    cudaFuncSetAttribute(out_mma_kernel, cudaFuncAttributeMaxDynamicSharedMemorySize, gemm_smem);
    out_mma_kernel<<<dim3(S_DIM / 128, C_DIM / 128, B_DIM), 256, gemm_smem>>>(Wo, bo, out);
}

// round 17
// speedup vs baseline: 1.3514x; 1.1164x over previous
#include <cuda_runtime.h>
#include <cstdint>
#include <math.h>

#define B_DIM   8
#define C_DIM   512
#define S_DIM   1024
#define N_HEADS 8
#define DH      64
#define GROUPS  32
#define CPG     16
#define EPS     1e-5f
#define LOG2E   1.4426950408889634f

#define ASTRIDE 36          // gemm smem stage stride (floats) per 32-k row
#define DSTRIDE 133         // gemm smem D-staging stride
#define KSTR    72          // attn Q/K smem row stride (2 chunks of 36; 16B-aligned)
#define VSTR    148         // attn V smem row stride (4 chunks of 36 + pad; 16B-aligned)
#define QTILE   256         // attn q-tile rows (16 warps x 16 rows)
#define CTRUNC  1.00048828125f   // 1 + 2^-11: centers tf32 truncation error

// ---------------- device scratch (no allocation allowed) ----------------
__device__ float g_mean[B_DIM * GROUPS];
__device__ float g_rstd[B_DIM * GROUPS];
__device__ float g_xT [(size_t)B_DIM * S_DIM * C_DIM];   // [b,s,c] raw
__device__ float g_xnT[(size_t)B_DIM * S_DIM * C_DIM];   // [b,s,c] group-normed
__device__ float g_Q[(size_t)B_DIM * N_HEADS * S_DIM * DH];   // [b,h,s,d]
__device__ float g_K[(size_t)B_DIM * N_HEADS * S_DIM * DH];   // [b,h,s,d] (pre-scaled CTRUNC)
__device__ float g_V[(size_t)B_DIM * N_HEADS * DH * S_DIM];   // [b,h,d,s] (transposed, CTRUNC)
__device__ float g_ctx[(size_t)B_DIM * S_DIM * C_DIM];   // [b,s,c]

// ---------------- helpers ----------------
__device__ __forceinline__ uint32_t f2tf32(float f) {
    uint32_t r;
    asm("cvt.rna.tf32.f32 %0, %1;" : "=r"(r) : "f"(f));
    return r;
}

__device__ __forceinline__ void mma_tf32(float c[4], const uint32_t a[4], const uint32_t b[2]) {
    asm volatile(
        "mma.sync.aligned.m16n8k8.row.col.f32.tf32.tf32.f32 "
        "{%0,%1,%2,%3},{%4,%5,%6,%7},{%8,%9},{%0,%1,%2,%3};"
        : "+f"(c[0]), "+f"(c[1]), "+f"(c[2]), "+f"(c[3])
        : "r"(a[0]), "r"(a[1]), "r"(a[2]), "r"(a[3]), "r"(b[0]), "r"(b[1]));
}

#define CP16(dst_u32, src_ptr) \
    asm volatile("cp.async.cg.shared.global [%0], [%1], 16;" \
        :: "r"(dst_u32), "l"((uint64_t)__cvta_generic_to_global(src_ptr)))
#define CP_COMMIT()  asm volatile("cp.async.commit_group;" ::: "memory")
#define CP_WAIT0()   asm volatile("cp.async.wait_group 0;" ::: "memory")

// ============================================================================
// 1) GroupNorm statistics
// ============================================================================
__global__ void gn_stats_kernel(const float* __restrict__ x) {
    int bg = blockIdx.x;
    const float4* p = (const float4*)(x + (size_t)bg * CPG * S_DIM);
    const int n4 = CPG * S_DIM / 4;
    float s = 0.f, s2 = 0.f;
    for (int i = threadIdx.x; i < n4; i += 256) {
        float4 v = p[i];
        s  += v.x + v.y + v.z + v.w;
        s2 += v.x * v.x + v.y * v.y + v.z * v.z + v.w * v.w;
    }
    __shared__ float ss[256], sq[256];
    ss[threadIdx.x] = s; sq[threadIdx.x] = s2;
    __syncthreads();
    for (int o = 128; o > 0; o >>= 1) {
        if (threadIdx.x < o) { ss[threadIdx.x] += ss[threadIdx.x + o]; sq[threadIdx.x] += sq[threadIdx.x + o]; }
        __syncthreads();
    }
    if (threadIdx.x == 0) {
        const float invN = 1.f / (CPG * S_DIM);
        float mean = ss[0] * invN;
        float var  = sq[0] * invN - mean * mean;
        g_mean[bg] = mean;
        g_rstd[bg] = rsqrtf(var + EPS);
    }
}

// ============================================================================
// 2) x transpose [b,c,s] -> [b,s,c], raw + GroupNormed (fp32)
// ============================================================================
__global__ void prep_x_kernel(const float* __restrict__ x,
                              const float* __restrict__ gw, const float* __restrict__ gb) {
    __shared__ float t[32][33];
    int b = blockIdx.z, s0 = blockIdx.x * 32, c0 = blockIdx.y * 32;
    const float* xb = x + ((size_t)b * C_DIM + c0) * S_DIM + s0;
    #pragma unroll
    for (int j = 0; j < 4; ++j) {
        int c = threadIdx.y + j * 8;
        t[c][threadIdx.x] = xb[(size_t)c * S_DIM + threadIdx.x];
    }
    __syncthreads();
    int c = c0 + threadIdx.x;
    float w = gw[c], bia = gb[c];
    int gi = b * GROUPS + (c >> 4);
    float mu = g_mean[gi], rs = g_rstd[gi];
    #pragma unroll
    for (int j = 0; j < 4; ++j) {
        int s = s0 + threadIdx.y + j * 8;
        float v = t[threadIdx.x][threadIdx.y + j * 8];
        size_t o = ((size_t)b * S_DIM + s) * C_DIM + c;
        g_xT[o]  = v;
        g_xnT[o] = (v - mu) * rs * w + bia;
    }
}

// ============================================================================
// tf32 mma.sync GEMM core (proven R3): D[128,128] = A[128,512]*B[128,512]^T
// ============================================================================
__device__ __forceinline__ void gemm_mainloop(
    const float* __restrict__ Ag, const float* __restrict__ Bg,
    uint32_t* As, uint32_t* Bs, float acc[4][4][4])
{
    const int tid  = threadIdx.x;
    const int lane = tid & 31;
    const int warp = tid >> 5;
    const int my = warp >> 2, wx = warp & 3;
    const int tg = lane & 3, gp = lane >> 2;
    float4 pa[4], pb[4];

#define LDG_STAGE(k0_) do { \
    _Pragma("unroll") \
    for (int it = 0; it < 4; ++it) { \
        int idx = it * 256 + tid; \
        int row = idx >> 3, cq = idx & 7; \
        pa[it] = *(const float4*)(Ag + (size_t)row * C_DIM + (k0_) + cq * 4); \
        pb[it] = *(const float4*)(Bg + (size_t)row * C_DIM + (k0_) + cq * 4); \
    } \
} while (0)

#define STS_STAGE(buf_) do { \
    uint32_t* Ad = As + (buf_) * (128 * ASTRIDE); \
    uint32_t* Bd = Bs + (buf_) * (128 * ASTRIDE); \
    _Pragma("unroll") \
    for (int it = 0; it < 4; ++it) { \
        int idx = it * 256 + tid; \
        int row = idx >> 3, cq = idx & 7; \
        int base = row * ASTRIDE + (cq >> 1) * 8 + (cq & 1); \
        float av[4] = {pa[it].x, pa[it].y, pa[it].z, pa[it].w}; \
        float bv[4] = {pb[it].x, pb[it].y, pb[it].z, pb[it].w}; \
        _Pragma("unroll") \
        for (int j = 0; j < 4; ++j) { \
            Ad[base + 2 * j] = f2tf32(av[j]); \
            Bd[base + 2 * j] = f2tf32(bv[j]); \
        } \
    } \
} while (0)

    LDG_STAGE(0);
    STS_STAGE(0);
    LDG_STAGE(32);
    __syncthreads();

    const int NSTAGE = C_DIM / 32;
    for (int s = 0; s < NSTAGE; ++s) {
        const uint32_t* Ab = As + (s & 1) * (128 * ASTRIDE);
        const uint32_t* Bb = Bs + (s & 1) * (128 * ASTRIDE);
        #pragma unroll
        for (int k8 = 0; k8 < 4; ++k8) {
            uint32_t af[4][4];
            #pragma unroll
            for (int mi = 0; mi < 4; ++mi) {
                int row = my * 64 + mi * 16 + gp;
                uint2 lo = *(const uint2*)&Ab[row * ASTRIDE + k8 * 8 + tg * 2];
                uint2 hi = *(const uint2*)&Ab[(row + 8) * ASTRIDE + k8 * 8 + tg * 2];
                af[mi][0] = lo.x; af[mi][1] = hi.x; af[mi][2] = lo.y; af[mi][3] = hi.y;
            }
            uint32_t bf[4][2];
            #pragma unroll
            for (int nj = 0; nj < 4; ++nj) {
                int col = wx * 32 + nj * 8 + gp;
                uint2 bb = *(const uint2*)&Bb[col * ASTRIDE + k8 * 8 + tg * 2];
                bf[nj][0] = bb.x; bf[nj][1] = bb.y;
            }
            #pragma unroll
            for (int mi = 0; mi < 4; ++mi)
                #pragma unroll
                for (int nj = 0; nj < 4; ++nj)
                    mma_tf32(acc[mi][nj], af[mi], bf[nj]);
        }
        if (s + 1 < NSTAGE) STS_STAGE((s + 1) & 1);
        if (s + 2 < NSTAGE) LDG_STAGE((s + 2) * 32);
        __syncthreads();
    }
#undef LDG_STAGE
#undef STS_STAGE
}

__device__ __forceinline__ void stage_D(float* Ds, const float acc[4][4][4]) {
    const int lane = threadIdx.x & 31;
    const int warp = threadIdx.x >> 5;
    const int my = warp >> 2, wx = warp & 3;
    const int tg = lane & 3, gp = lane >> 2;
    #pragma unroll
    for (int mi = 0; mi < 4; ++mi) {
        int r = my * 64 + mi * 16 + gp;
        #pragma unroll
        for (int nj = 0; nj < 4; ++nj) {
            int c = wx * 32 + nj * 8 + tg * 2;
            Ds[r * DSTRIDE + c]           = acc[mi][nj][0];
            Ds[r * DSTRIDE + c + 1]       = acc[mi][nj][1];
            Ds[(r + 8) * DSTRIDE + c]     = acc[mi][nj][2];
            Ds[(r + 8) * DSTRIDE + c + 1] = acc[mi][nj][3];
        }
    }
}

// ============================================================================
// 3) QKV projection. Q,K stored [b,h,s,d]; V stored transposed [b,h,d,s].
//    K and V pre-scaled by CTRUNC to center tf32-truncation in attention.
// ============================================================================
__global__ void __launch_bounds__(256, 2) qkv_mma_kernel(const float* __restrict__ Wq,
                                                         const float* __restrict__ Wk,
                                                         const float* __restrict__ Wv) {
    extern __shared__ uint32_t sm[];
    uint32_t* As = sm;
    uint32_t* Bs = sm + 2 * 128 * ASTRIDE;

    int z = blockIdx.z;
    int mat = z % 3, b = z / 3;
    int co0 = blockIdx.y * 128, s0 = blockIdx.x * 128;

    const float* W  = (mat == 0) ? Wq : (mat == 1) ? Wk : Wv;
    const float* Bt = ((mat == 0) ? g_xnT : g_xT) + (size_t)b * S_DIM * C_DIM;
    const float* Ag = W + (size_t)co0 * C_DIM;
    const float* Bg = Bt + (size_t)s0 * C_DIM;

    float acc[4][4][4] = {};
    gemm_mainloop(Ag, Bg, As, Bs, acc);

    float* Ds = (float*)sm;
    stage_D(Ds, acc);
    __syncthreads();

    int tid = threadIdx.x;
    if (mat == 2) {
        // Vt[b,h,d,s]: rows co_l = (h_l, d), cols = s  (coalesced along s)
        #pragma unroll
        for (int it = 0; it < 16; ++it) {
            int i = it * 256 + tid;
            int s4 = (i & 31) * 4, co_l = i >> 5;
            int h = (co0 >> 6) + (co_l >> 6), d = co_l & 63;
            float4 v = make_float4(Ds[co_l * DSTRIDE + s4]     * CTRUNC,
                                   Ds[co_l * DSTRIDE + s4 + 1] * CTRUNC,
                                   Ds[co_l * DSTRIDE + s4 + 2] * CTRUNC,
                                   Ds[co_l * DSTRIDE + s4 + 3] * CTRUNC);
            *(float4*)&g_V[(((size_t)(b * N_HEADS + h)) * DH + d) * S_DIM + s0 + s4] = v;
        }
    } else {
        float* dst = (mat == 0) ? g_Q : g_K;
        const float fac = (mat == 0) ? 1.f : CTRUNC;
        #pragma unroll
        for (int it = 0; it < 16; ++it) {
            int i = it * 256 + tid;
            int d0  = (i & 15) * 4;
            int s_l = (i >> 4) & 127;
            int h_l = i >> 11;
            int row = h_l * 64 + d0;
            float4 v = make_float4(Ds[row * DSTRIDE + s_l]       * fac,
                                   Ds[(row + 1) * DSTRIDE + s_l] * fac,
                                   Ds[(row + 2) * DSTRIDE + s_l] * fac,
                                   Ds[(row + 3) * DSTRIDE + s_l] * fac);
            int h = (co0 >> 6) + h_l;
            int s = s0 + s_l;
            *(float4*)&dst[(((size_t)(b * N_HEADS + h)) * S_DIM + s) * DH + d0] = v;
        }
    }
}

// ============================================================================
// 4) Tensor-core flash attention v5: q-tile 256, kv-tile 128, 16 warps.
//    K/V staged raw via cp.async (tf32 truncation, error centered by CTRUNC),
//    double-buffered so tile t+1's copy overlaps tile t's compute.
// ============================================================================
__global__ void __launch_bounds__(512, 1) attn_mma_kernel() {
    extern __shared__ float sm_f[];
    uint32_t* Qs = (uint32_t*)sm_f;            // QTILE * KSTR
    uint32_t* Ks = Qs + QTILE * KSTR;          // 2 x 128 * KSTR
    uint32_t* Vs = Ks + 2 * 128 * KSTR;        // 2 x 64 * VSTR
    const uint32_t smem_u32 = (uint32_t)__cvta_generic_to_shared(sm_f);
    const uint32_t ks_base = smem_u32 + QTILE * KSTR * 4;
    const uint32_t vs_base = ks_base + 2 * 128 * KSTR * 4;

    const int tid = threadIdx.x;
    const int lane = tid & 31, warp = tid >> 5;     // warp 0..15
    const int tg = lane & 3, gp = lane >> 2;
    const int bh = blockIdx.y;
    const int b = bh >> 3, h = bh & 7;
    const int s0 = blockIdx.x * QTILE;
    const int r0 = warp * 16 + gp, r1 = r0 + 8;     // this thread's two q-rows

    const float* Qg  = g_Q + (size_t)bh * S_DIM * DH;
    const float* Kg  = g_K + (size_t)bh * S_DIM * DH;
    const float* Vtg = g_V + (size_t)bh * DH * S_DIM;   // [d][s]

    // cp.async staging of one K/V tile into buffer `buf`
#define STAGE_KV(t0_, buf_) do { \
    _Pragma("unroll") \
    for (int it = 0; it < 4; ++it) { \
        int idx = it * 512 + tid; \
        int row = idx >> 4, f4 = idx & 15; \
        uint32_t dst = ks_base + (buf_) * (128 * KSTR * 4) \
                     + (row * KSTR + (f4 >> 3) * 36 + (f4 & 7) * 4) * 4; \
        CP16(dst, Kg + (size_t)((t0_) + row) * DH + f4 * 4); \
    } \
    _Pragma("unroll") \
    for (int it = 0; it < 4; ++it) { \
        int idx = it * 512 + tid; \
        int d = idx >> 5, f4 = idx & 31; \
        uint32_t dst = vs_base + (buf_) * (64 * VSTR * 4) \
                     + (d * VSTR + (f4 >> 3) * 36 + (f4 & 7) * 4) * 4; \
        CP16(dst, Vtg + (size_t)d * S_DIM + (t0_) + f4 * 4); \
    } \
} while (0)

    // issue tile 0 copy immediately, then stage Q while it flies
    STAGE_KV(0, 0);
    CP_COMMIT();

    // Q tile: tf32 (rounded), linear in-chunk, scaled by 1/8 * log2(e)
    const float qscale = 0.125f * LOG2E;
    #pragma unroll
    for (int it = 0; it < 8; ++it) {
        int idx = it * 512 + tid;
        int row = idx >> 4, f4 = idx & 15;
        float4 v = *(const float4*)(Qg + (size_t)(s0 + row) * DH + f4 * 4);
        uint32_t* p = Qs + row * KSTR + (f4 >> 3) * 36 + (f4 & 7) * 4;
        *(uint2*)(p)     = make_uint2(f2tf32(v.x * qscale), f2tf32(v.y * qscale));
        *(uint2*)(p + 2) = make_uint2(f2tf32(v.z * qscale), f2tf32(v.w * qscale));
    }

    float m0 = -1e30f, m1 = -1e30f, l0 = 0.f, l1 = 0.f;
    float o_acc[8][4] = {};

    for (int it8 = 0; it8 < 8; ++it8) {
        CP_WAIT0();        // tile it8 resident
        __syncthreads();   // all warps: tile visible AND old buffer reads done
        if (it8 < 7) { STAGE_KV((it8 + 1) * 128, (it8 + 1) & 1); CP_COMMIT(); }

        const uint32_t* Kb = Ks + (it8 & 1) * (128 * KSTR);
        const uint32_t* Vb = Vs + (it8 & 1) * (64 * VSTR);

        // ---- S = Q K^T : warp covers rows r0/r1, all 128 kv cols ----
        float s_acc[16][4] = {};
        #pragma unroll
        for (int k8 = 0; k8 < 8; ++k8) {
            int koff = (k8 >> 2) * 36 + (k8 & 3) * 8 + tg * 2;
            uint2 lo = *(const uint2*)&Qs[r0 * KSTR + koff];
            uint2 hi = *(const uint2*)&Qs[r1 * KSTR + koff];
            uint32_t af[4] = {lo.x, hi.x, lo.y, hi.y};
            #pragma unroll
            for (int nj = 0; nj < 16; ++nj) {
                int col = nj * 8 + gp;
                uint2 bb = *(const uint2*)&Kb[col * KSTR + koff];
                uint32_t bf[2] = {bb.x, bb.y};
                mma_tf32(s_acc[nj], af, bf);
            }
        }

        // ---- register softmax (log2 domain) ----
        float mx0 = -1e30f, mx1 = -1e30f;
        #pragma unroll
        for (int nj = 0; nj < 16; ++nj) {
            mx0 = fmaxf(mx0, fmaxf(s_acc[nj][0], s_acc[nj][1]));
            mx1 = fmaxf(mx1, fmaxf(s_acc[nj][2], s_acc[nj][3]));
        }
        mx0 = fmaxf(mx0, __shfl_xor_sync(0xffffffffu, mx0, 1));
        mx0 = fmaxf(mx0, __shfl_xor_sync(0xffffffffu, mx0, 2));
        mx1 = fmaxf(mx1, __shfl_xor_sync(0xffffffffu, mx1, 1));
        mx1 = fmaxf(mx1, __shfl_xor_sync(0xffffffffu, mx1, 2));
        float m0n = fmaxf(m0, mx0), m1n = fmaxf(m1, mx1);
        float c0 = exp2f(m0 - m0n), c1 = exp2f(m1 - m1n);
        float sum0 = 0.f, sum1 = 0.f;
        #pragma unroll
        for (int nj = 0; nj < 16; ++nj) {
            float p0 = exp2f(s_acc[nj][0] - m0n);
            float p1 = exp2f(s_acc[nj][1] - m0n);
            float p2 = exp2f(s_acc[nj][2] - m1n);
            float p3 = exp2f(s_acc[nj][3] - m1n);
            s_acc[nj][0] = p0; s_acc[nj][1] = p1;
            s_acc[nj][2] = p2; s_acc[nj][3] = p3;
            sum0 += p0 + p1; sum1 += p2 + p3;
        }
        sum0 += __shfl_xor_sync(0xffffffffu, sum0, 1);
        sum0 += __shfl_xor_sync(0xffffffffu, sum0, 2);
        sum1 += __shfl_xor_sync(0xffffffffu, sum1, 1);
        sum1 += __shfl_xor_sync(0xffffffffu, sum1, 2);
        l0 = l0 * c0 + sum0; l1 = l1 * c1 + sum1;
        m0 = m0n; m1 = m1n;
        #pragma unroll
        for (int nj = 0; nj < 8; ++nj) {
            o_acc[nj][0] *= c0; o_acc[nj][1] *= c0;
            o_acc[nj][2] *= c1; o_acc[nj][3] *= c1;
        }

        // ---- O += P V : A-fragments straight from s_acc ----
        #pragma unroll
        for (int k8 = 0; k8 < 16; ++k8) {
            uint32_t af[4] = { f2tf32(s_acc[k8][0]), f2tf32(s_acc[k8][2]),
                               f2tf32(s_acc[k8][1]), f2tf32(s_acc[k8][3]) };
            int koff = (k8 >> 2) * 36 + (k8 & 3) * 8 + tg * 2;
            #pragma unroll
            for (int njd = 0; njd < 8; ++njd) {
                int col = njd * 8 + gp;     // d index
                uint2 bb = *(const uint2*)&Vb[col * VSTR + koff];
                uint32_t bf[2] = {bb.x, bb.y};
                mma_tf32(o_acc[njd], af, bf);
            }
        }
    }
#undef STAGE_KV

    // ---- epilogue: normalize, stage into Qs (stride KSTR), coalesced store ----
    __syncthreads();
    float* Ds = (float*)Qs;
    float inv0 = 1.f / l0, inv1 = 1.f / l1;
    #pragma unroll
    for (int nj = 0; nj < 8; ++nj) {
        int c = nj * 8 + tg * 2;
        Ds[r0 * KSTR + c]     = o_acc[nj][0] * inv0;
        Ds[r0 * KSTR + c + 1] = o_acc[nj][1] * inv0;
        Ds[r1 * KSTR + c]     = o_acc[nj][2] * inv1;
        Ds[r1 * KSTR + c + 1] = o_acc[nj][3] * inv1;
    }
    __syncthreads();
    float* cb = g_ctx + ((size_t)b * S_DIM + s0) * C_DIM + h * DH;
    #pragma unroll
    for (int it = 0; it < 8; ++it) {
        int idx = it * 512 + tid;
        int r = idx >> 4, c4 = (idx & 15) * 4;
        float4 v = make_float4(Ds[r * KSTR + c4],     Ds[r * KSTR + c4 + 1],
                               Ds[r * KSTR + c4 + 2], Ds[r * KSTR + c4 + 3]);
        *(float4*)(cb + (size_t)r * C_DIM + c4) = v;
    }
}

// ============================================================================
// 5) Output projection ((256,2) for 2 CTAs/SM)
// ============================================================================
__global__ void __launch_bounds__(256, 2) out_mma_kernel(const float* __restrict__ Wo,
                                                         const float* __restrict__ bo,
                                                         float* __restrict__ out) {
    extern __shared__ uint32_t sm[];
    uint32_t* As = sm;
    uint32_t* Bs = sm + 2 * 128 * ASTRIDE;

    int b = blockIdx.z;
    int co0 = blockIdx.y * 128, s0 = blockIdx.x * 128;

    const float* Ag = Wo + (size_t)co0 * C_DIM;
    const float* Bg = g_ctx + ((size_t)b * S_DIM + s0) * C_DIM;

    float acc[4][4][4] = {};
    gemm_mainloop(Ag, Bg, As, Bs, acc);

    float* Ds = (float*)sm;
    stage_D(Ds, acc);
    __syncthreads();

    int tid = threadIdx.x;
    #pragma unroll
    for (int it = 0; it < 16; ++it) {
        int i = it * 256 + tid;
        int s4   = (i & 31) * 4;
        int co_l = i >> 5;
        float bias = bo[co0 + co_l];
        float4 v = make_float4(Ds[co_l * DSTRIDE + s4]     + bias,
                               Ds[co_l * DSTRIDE + s4 + 1] + bias,
                               Ds[co_l * DSTRIDE + s4 + 2] + bias,
                               Ds[co_l * DSTRIDE + s4 + 3] + bias);
        *(float4*)&out[((size_t)b * C_DIM + co0 + co_l) * S_DIM + s0 + s4] = v;
    }
}

// ============================================================================
extern "C" void kernel_launch(void* const* d_in, const int* in_sizes, int n_in,
                              void* d_out, int out_size) {
    const float* x    = (const float*)d_in[0];
    const float* gn_w = (const float*)d_in[1];
    const float* gn_b = (const float*)d_in[2];
    const float* Wq   = (const float*)d_in[3];
    const float* Wk   = (const float*)d_in[4];
    const float* Wv   = (const float*)d_in[5];
    const float* Wo   = (const float*)d_in[6];
    const float* bo   = (const float*)d_in[7];
    float* out = (float*)d_out;

    const int gemm_smem = 4 * 128 * ASTRIDE * (int)sizeof(float);   // 73728 B
    const int attn_smem = (QTILE * KSTR + 2 * 128 * KSTR + 2 * 64 * VSTR)
                          * (int)sizeof(float);                     // 223232 B

    gn_stats_kernel<<<B_DIM * GROUPS, 256>>>(x);
    prep_x_kernel<<<dim3(S_DIM / 32, C_DIM / 32, B_DIM), dim3(32, 8)>>>(x, gn_w, gn_b);

    cudaFuncSetAttribute(qkv_mma_kernel, cudaFuncAttributeMaxDynamicSharedMemorySize, gemm_smem);
    qkv_mma_kernel<<<dim3(S_DIM / 128, C_DIM / 128, B_DIM * 3), 256, gemm_smem>>>(Wq, Wk, Wv);

    cudaFuncSetAttribute(attn_mma_kernel, cudaFuncAttributeMaxDynamicSharedMemorySize, attn_smem);
    attn_mma_kernel<<<dim3(S_DIM / QTILE, B_DIM * N_HEADS), 512, attn_smem>>>();

    cudaFuncSetAttribute(out_mma_kernel, cudaFuncAttributeMaxDynamicSharedMemorySize, gemm_smem);
    out_mma_kernel<<<dim3(S_DIM / 128, C_DIM / 128, B_DIM), 256, gemm_smem>>>(Wo, bo, out);
}